// round 6
// baseline (speedup 1.0000x reference)
#include <cuda_runtime.h>
#include <math.h>

#define N_NODES 50000
#define N_EDGES 800000
#define NBLK    ((N_NODES + 255) / 256)   // 196 scan blocks

// ---------------- scratch (__device__ globals; float4-typed for alignment) ----------------
__device__ int    g_idx64;                        // 1 if edge_index is int64, 0 if int32
__device__ int    g_deg[N_NODES];
__device__ float  g_invdeg[N_NODES];
__device__ int    g_rowptr[N_NODES + 1];
__device__ int    g_cursor[N_NODES];
__device__ int    g_src[N_EDGES];
__device__ int    g_bsum[256];                    // per-block degree sums (NBLK <= 256)
__device__ int    g_boff[256];                    // exclusive offsets per block
__device__ float4 g_agg4[(size_t)N_NODES * 32];   // up to 128 ch per node
__device__ float4 g_ha4 [(size_t)N_NODES * 32];
__device__ float4 g_hb4 [(size_t)N_NODES * 32];

// ---------------- f32x2 packed helpers ----------------
typedef unsigned long long u64;
__device__ __forceinline__ u64 pack2(float lo, float hi) {
    u64 r; asm("mov.b64 %0, {%1,%2};" : "=l"(r) : "f"(lo), "f"(hi)); return r;
}
__device__ __forceinline__ u64 fma2(u64 a, u64 b, u64 c) {
    u64 d; asm("fma.rn.f32x2 %0, %1, %2, %3;" : "=l"(d) : "l"(a), "l"(b), "l"(c)); return d;
}
__device__ __forceinline__ float2 unpack2(u64 v) {
    float2 f; asm("mov.b64 {%0,%1}, %2;" : "=f"(f.x), "=f"(f.y) : "l"(v)); return f;
}

// ---------------- edge-index dtype detection (warp-parallel, one ballot) ----------------
__global__ void k_detect(const unsigned int* __restrict__ w) {
    int lane = threadIdx.x & 31;
    unsigned int v = w[2 * lane + 1] | w[2 * (lane + 32) + 1] |
                     w[2 * (lane + 64) + 1] | w[2 * (lane + 96) + 1];
    unsigned int any = __ballot_sync(0xffffffffu, v != 0u);
    if (lane == 0) g_idx64 = (any == 0u) ? 1 : 0;
}

__device__ __forceinline__ int clampi(int v, int lo, int hi) {
    return v < lo ? lo : (v > hi ? hi : v);
}
__device__ __forceinline__ int edge_at(const void* ei, long long pos) {
    int v;
    if (g_idx64) v = (int)((const long long*)ei)[pos];
    else         v = ((const int*)ei)[pos];
    return clampi(v, 0, N_NODES - 1);
}

// ---------------- CSR build ----------------
__global__ void k_zero_deg() {
    int i = blockIdx.x * blockDim.x + threadIdx.x;
    if (i < N_NODES) g_deg[i] = 0;
}

__global__ void k_count(const void* __restrict__ ei) {
    int e = blockIdx.x * blockDim.x + threadIdx.x;
    if (e < N_EDGES) {
        int d = edge_at(ei, (long long)N_EDGES + e);
        atomicAdd(&g_deg[d], 1);
    }
}

__global__ void k_bsum() {
    __shared__ int sh[256];
    int i = blockIdx.x * 256 + threadIdx.x;
    sh[threadIdx.x] = (i < N_NODES) ? g_deg[i] : 0;
    __syncthreads();
    for (int off = 128; off > 0; off >>= 1) {
        if (threadIdx.x < off) sh[threadIdx.x] += sh[threadIdx.x + off];
        __syncthreads();
    }
    if (threadIdx.x == 0) g_bsum[blockIdx.x] = sh[0];
}

__global__ void k_bscan() {
    __shared__ int sh[256];
    int t = threadIdx.x;
    int v = (t < NBLK) ? g_bsum[t] : 0;
    sh[t] = v;
    __syncthreads();
    for (int off = 1; off < 256; off <<= 1) {
        int u = (t >= off) ? sh[t - off] : 0;
        __syncthreads();
        sh[t] += u;
        __syncthreads();
    }
    if (t < NBLK) g_boff[t] = sh[t] - v;   // exclusive
    if (t == 0)   g_rowptr[N_NODES] = N_EDGES;
}

__global__ void k_scatter() {
    __shared__ int sh[256];
    int t = threadIdx.x;
    int i = blockIdx.x * 256 + t;
    int d = (i < N_NODES) ? g_deg[i] : 0;
    sh[t] = d;
    __syncthreads();
    for (int off = 1; off < 256; off <<= 1) {
        int u = (t >= off) ? sh[t - off] : 0;
        __syncthreads();
        sh[t] += u;
        __syncthreads();
    }
    if (i < N_NODES) {
        int base = g_boff[blockIdx.x] + sh[t] - d;
        g_rowptr[i] = base;
        g_cursor[i] = base;
        g_invdeg[i] = 1.0f / fmaxf((float)d, 1.0f);
    }
}

__global__ void k_fill(const void* __restrict__ ei) {
    int e = blockIdx.x * blockDim.x + threadIdx.x;
    if (e < N_EDGES) {
        int s = edge_at(ei, e);
        int d = edge_at(ei, (long long)N_EDGES + e);
        int pos = atomicAdd(&g_cursor[d], 1);
        pos = clampi(pos, 0, N_EDGES - 1);
        g_src[pos] = s;
    }
}

// ---------------- atomic-free mean aggregation: one warp per node ----------------
// SSEL: 0 = xparam (harness input), 1 = g_ha4, 2 = g_hb4. Output: g_agg4.
template <int C, int SSEL>
__global__ void k_agg(const float4* __restrict__ xparam4) {
    const float4* feat = (SSEL == 0) ? xparam4 : (SSEL == 1) ? (const float4*)g_ha4
                                                             : (const float4*)g_hb4;
    int w    = (blockIdx.x * blockDim.x + threadIdx.x) >> 5;
    int lane = threadIdx.x & 31;
    if (w >= N_NODES) return;
    int beg = g_rowptr[w], end = g_rowptr[w + 1];
    if (C == 128) {
        float4 a = make_float4(0.f, 0.f, 0.f, 0.f);
        int e = beg;
        for (; e + 1 < end; e += 2) {
            int s0 = g_src[e];
            int s1 = g_src[e + 1];
            float4 v0 = feat[(size_t)s0 * 32 + lane];
            float4 v1 = feat[(size_t)s1 * 32 + lane];
            a.x += v0.x; a.y += v0.y; a.z += v0.z; a.w += v0.w;
            a.x += v1.x; a.y += v1.y; a.z += v1.z; a.w += v1.w;
        }
        if (e < end) {
            int s0 = g_src[e];
            float4 v0 = feat[(size_t)s0 * 32 + lane];
            a.x += v0.x; a.y += v0.y; a.z += v0.z; a.w += v0.w;
        }
        float iv = g_invdeg[w];
        a.x *= iv; a.y *= iv; a.z *= iv; a.w *= iv;
        g_agg4[(size_t)w * 32 + lane] = a;
    } else { // C == 64
        const float2* f2 = (const float2*)feat;
        float2 a = make_float2(0.f, 0.f);
        int e = beg;
        for (; e + 1 < end; e += 2) {
            int s0 = g_src[e];
            int s1 = g_src[e + 1];
            float2 v0 = f2[(size_t)s0 * 32 + lane];
            float2 v1 = f2[(size_t)s1 * 32 + lane];
            a.x += v0.x; a.y += v0.y;
            a.x += v1.x; a.y += v1.y;
        }
        if (e < end) {
            int s0 = g_src[e];
            float2 v0 = f2[(size_t)s0 * 32 + lane];
            a.x += v0.x; a.y += v0.y;
        }
        float iv = g_invdeg[w];
        a.x *= iv; a.y *= iv;
        ((float2*)g_agg4)[(size_t)w * 32 + lane] = a;
    }
}

// ---------------- fused SAGE GEMM (f32x2 core, vectorized LDS) -------------------------------
// out = mean@Wl^T + bl + x@Wr^T (+relu / +log_softmax)
// 256 threads/block, one BM-node tile per block, K in KC=16 chunks.
// Thread owns R=8 rows x 4 output channels (2 f32x2 accumulators per row).
// Weight smem rows [k][co] are 16B-aligned; a ulonglong2 load yields both f32x2 operands.
// Value smem read as one float4 broadcast per row per 4 k-steps.
template <int CIN, int COUT, int BM, bool RELU, bool LSM, int XSEL, int OSEL>
__launch_bounds__(256, 1)
__global__ void k_gemm(const float4* __restrict__ xparam4,
                       const float* __restrict__ Wl, const float* __restrict__ bl,
                       const float* __restrict__ Wr, float* __restrict__ outparam) {
    constexpr int KC    = 16;                 // K-chunk (floats)
    constexpr int KQ    = KC / 4;             // K-chunk in float4
    constexpr int NCG   = COUT / 4;           // channel groups
    constexpr int NGR   = 256 / NCG;          // node groups
    constexpr int R     = BM / NGR;           // rows per thread (== 8)
    constexpr int COUTP = COUT + 4;           // pad (row stride stays a 16B multiple)
    constexpr int C4    = CIN / 4;

    __shared__ float Wl_s[KC][COUTP];
    __shared__ float Wr_s[KC][COUTP];
    __shared__ float vm_s[BM][KC];
    __shared__ float vx_s[BM][KC];

    const float4* xin4  = (XSEL == 0) ? xparam4 : (XSEL == 1) ? (const float4*)g_ha4
                                                              : (const float4*)g_hb4;
    const float4* mean4 = (const float4*)g_agg4;
    float*        out   = (OSEL == 0) ? outparam : (OSEL == 1) ? (float*)g_ha4
                                                               : (float*)g_hb4;

    const int tid = threadIdx.x;
    const int cg  = tid % NCG;
    const int ng  = tid / NCG;
    const int nb  = blockIdx.x * BM;

    u64 acc[R][2];
    {
        const u64 b0 = ((const u64*)bl)[cg * 2];
        const u64 b1 = ((const u64*)bl)[cg * 2 + 1];
        #pragma unroll
        for (int r = 0; r < R; r++) { acc[r][0] = b0; acc[r][1] = b1; }
    }

    for (int kb4 = 0; kb4 < C4; kb4 += KQ) {
        __syncthreads();
        // stage weight K-panels: Wl/Wr are [co][ci] row-major; smem is [k][co]
        for (int idx = tid; idx < KC * COUT; idx += 256) {
            int co = idx / KC;
            int k  = idx % KC;
            Wl_s[k][co] = Wl[co * CIN + kb4 * 4 + k];
            Wr_s[k][co] = Wr[co * CIN + kb4 * 4 + k];
        }
        // stage value tiles (float4 stores; rows are 64B, aligned)
        for (int idx = tid; idx < BM * KQ; idx += 256) {
            int nl = idx / KQ;
            int q  = idx % KQ;
            int n  = nb + nl; if (n >= N_NODES) n = N_NODES - 1;
            *(float4*)&vm_s[nl][q * 4] = mean4[(size_t)n * C4 + kb4 + q];
            *(float4*)&vx_s[nl][q * 4] = xin4 [(size_t)n * C4 + kb4 + q];
        }
        __syncthreads();

        #pragma unroll
        for (int kq = 0; kq < KQ; kq++) {
            // weights for 4 consecutive k: one LDS.128 per matrix per k
            ulonglong2 wl[4], wr[4];
            #pragma unroll
            for (int j = 0; j < 4; j++) {
                wl[j] = *(const ulonglong2*)&Wl_s[kq * 4 + j][cg * 4];
                wr[j] = *(const ulonglong2*)&Wr_s[kq * 4 + j][cg * 4];
            }
            #pragma unroll
            for (int r = 0; r < R; r++) {
                const float4 m = *(const float4*)&vm_s[ng * R + r][kq * 4];
                const float4 x = *(const float4*)&vx_s[ng * R + r][kq * 4];
                u64 a0 = acc[r][0], a1 = acc[r][1];
                u64 t;
                t = pack2(m.x, m.x); a0 = fma2(t, wl[0].x, a0); a1 = fma2(t, wl[0].y, a1);
                t = pack2(x.x, x.x); a0 = fma2(t, wr[0].x, a0); a1 = fma2(t, wr[0].y, a1);
                t = pack2(m.y, m.y); a0 = fma2(t, wl[1].x, a0); a1 = fma2(t, wl[1].y, a1);
                t = pack2(x.y, x.y); a0 = fma2(t, wr[1].x, a0); a1 = fma2(t, wr[1].y, a1);
                t = pack2(m.z, m.z); a0 = fma2(t, wl[2].x, a0); a1 = fma2(t, wl[2].y, a1);
                t = pack2(x.z, x.z); a0 = fma2(t, wr[2].x, a0); a1 = fma2(t, wr[2].y, a1);
                t = pack2(m.w, m.w); a0 = fma2(t, wl[3].x, a0); a1 = fma2(t, wl[3].y, a1);
                t = pack2(x.w, x.w); a0 = fma2(t, wr[3].x, a0); a1 = fma2(t, wr[3].y, a1);
                acc[r][0] = a0; acc[r][1] = a1;
            }
        }
    }

    // epilogue
    #pragma unroll
    for (int r = 0; r < R; r++) {
        int n = nb + ng * R + r;
        float2 a = unpack2(acc[r][0]);
        float2 b = unpack2(acc[r][1]);
        float v0 = a.x, v1 = a.y, v2 = b.x, v3 = b.y;
        if (RELU) {
            v0 = fmaxf(v0, 0.f); v1 = fmaxf(v1, 0.f);
            v2 = fmaxf(v2, 0.f); v3 = fmaxf(v3, 0.f);
        }
        if (LSM) {
            // NCG==16: the 16 lanes owning one row form a contiguous shfl subgroup
            float mx = fmaxf(fmaxf(v0, v1), fmaxf(v2, v3));
            #pragma unroll
            for (int m = 1; m < 16; m <<= 1)
                mx = fmaxf(mx, __shfl_xor_sync(0xffffffffu, mx, m));
            float s = expf(v0 - mx) + expf(v1 - mx) + expf(v2 - mx) + expf(v3 - mx);
            #pragma unroll
            for (int m = 1; m < 16; m <<= 1)
                s += __shfl_xor_sync(0xffffffffu, s, m);
            float l = mx + logf(s);
            v0 -= l; v1 -= l; v2 -= l; v3 -= l;
        }
        if (n < N_NODES) {
            float4 o = make_float4(v0, v1, v2, v3);
            *(float4*)&out[(size_t)n * COUT + cg * 4] = o;
        }
    }
}

// ---------------- launch ----------------
extern "C" void kernel_launch(void* const* d_in, const int* in_sizes, int n_in,
                              void* d_out, int out_size) {
    (void)in_sizes; (void)n_in; (void)out_size;
    const float4* x4  = (const float4*)d_in[0];
    const void*   ei  = d_in[1];
    const float* Wl1 = (const float*)d_in[2];
    const float* bl1 = (const float*)d_in[3];
    const float* Wr1 = (const float*)d_in[4];
    const float* Wl2 = (const float*)d_in[5];
    const float* bl2 = (const float*)d_in[6];
    const float* Wr2 = (const float*)d_in[7];
    const float* Wl3 = (const float*)d_in[8];
    const float* bl3 = (const float*)d_in[9];
    const float* Wr3 = (const float*)d_in[10];
    const float* Wl4 = (const float*)d_in[11];
    const float* bl4 = (const float*)d_in[12];
    const float* Wr4 = (const float*)d_in[13];
    float* out = (float*)d_out;

    // dtype detect + CSR build (parallel scan)
    k_detect<<<1, 32>>>((const unsigned int*)ei);
    k_zero_deg<<<NBLK, 256>>>();
    k_count<<<(N_EDGES + 255) / 256, 256>>>(ei);
    k_bsum<<<NBLK, 256>>>();
    k_bscan<<<1, 256>>>();
    k_scatter<<<NBLK, 256>>>();
    k_fill<<<(N_EDGES + 255) / 256, 256>>>(ei);

    const int AGG_GRID = (N_NODES * 32 + 255) / 256;  // one warp per node
    const int G64  = (N_NODES + 63)  / 64;            // BM=64 tiles
    const int G128 = (N_NODES + 127) / 128;           // BM=128 tiles

    // L1: x -> ha, relu                (CIN=128, COUT=128, BM=64)
    k_agg<128,0><<<AGG_GRID, 256>>>(x4);
    k_gemm<128,128,64,true,false,0,1><<<G64, 256>>>(x4, Wl1, bl1, Wr1, nullptr);
    // L2: ha -> hb, relu (model-level relu after sage2)
    k_agg<128,1><<<AGG_GRID, 256>>>(nullptr);
    k_gemm<128,128,64,true,false,1,2><<<G64, 256>>>(nullptr, Wl2, bl2, Wr2, nullptr);
    // L3: hb -> ha, relu               (CIN=128, COUT=64, BM=128)
    k_agg<128,2><<<AGG_GRID, 256>>>(nullptr);
    k_gemm<128,64,128,true,false,2,1><<<G128, 256>>>(nullptr, Wl3, bl3, Wr3, nullptr);
    // L4: ha -> out, log_softmax       (CIN=64, COUT=64, BM=128)
    k_agg<64,1><<<AGG_GRID, 256>>>(nullptr);
    k_gemm<64,64,128,false,true,1,0><<<G128, 256>>>(nullptr, Wl4, bl4, Wr4, out);
}

// round 7
// speedup vs baseline: 1.3359x; 1.3359x over previous
#include <cuda_runtime.h>
#include <cuda_fp16.h>
#include <math.h>

#define N_NODES 50000
#define N_EDGES 800000
#define NBLK    ((N_NODES + 255) / 256)

// ---------------- scratch ----------------
__device__ int    g_idx64;
__device__ int    g_deg[N_NODES];
__device__ float  g_invdeg[N_NODES];
__device__ int    g_rowptr[N_NODES + 1];
__device__ int    g_cursor[N_NODES];
__device__ int    g_src[N_EDGES];
__device__ int    g_bsum[256];
__device__ int    g_boff[256];
// fp32 activation planes (aggregation inputs)
__device__ float  g_haf[(size_t)N_NODES * 128];
__device__ float  g_hbf[(size_t)N_NODES * 128];
// fp16 hi/lo planes (MMA inputs)
__device__ __half g_xh [(size_t)N_NODES * 128];
__device__ __half g_xl [(size_t)N_NODES * 128];
__device__ __half g_aggh[(size_t)N_NODES * 128];
__device__ __half g_aggl[(size_t)N_NODES * 128];
__device__ __half g_hah[(size_t)N_NODES * 128];
__device__ __half g_hal[(size_t)N_NODES * 128];
__device__ __half g_hbh[(size_t)N_NODES * 128];
__device__ __half g_hbl[(size_t)N_NODES * 128];
// split weights: per layer [Wl_hi | Wl_lo | Wr_hi | Wr_lo], each COUT*CIN
__device__ __half g_w16[180224];

// ---------------- helpers ----------------
__device__ __forceinline__ void split2(float v0, float v1, __half2& h, __half2& l) {
    __half h0 = __float2half_rn(v0), h1 = __float2half_rn(v1);
    h = __halves2half2(h0, h1);
    l = __halves2half2(__float2half_rn(v0 - __half2float(h0)),
                       __float2half_rn(v1 - __half2float(h1)));
}

__device__ __forceinline__ void mma16816(float* d, const unsigned* a, const unsigned* b) {
    asm volatile(
        "mma.sync.aligned.m16n8k16.row.col.f32.f16.f16.f32 "
        "{%0,%1,%2,%3},{%4,%5,%6,%7},{%8,%9},{%0,%1,%2,%3};"
        : "+f"(d[0]), "+f"(d[1]), "+f"(d[2]), "+f"(d[3])
        : "r"(a[0]), "r"(a[1]), "r"(a[2]), "r"(a[3]), "r"(b[0]), "r"(b[1]));
}

// ---------------- edge-index dtype detection ----------------
__global__ void k_detect(const unsigned int* __restrict__ w) {
    int lane = threadIdx.x & 31;
    unsigned int v = w[2 * lane + 1] | w[2 * (lane + 32) + 1] |
                     w[2 * (lane + 64) + 1] | w[2 * (lane + 96) + 1];
    unsigned int any = __ballot_sync(0xffffffffu, v != 0u);
    if (lane == 0) g_idx64 = (any == 0u) ? 1 : 0;
}

__device__ __forceinline__ int clampi(int v, int lo, int hi) {
    return v < lo ? lo : (v > hi ? hi : v);
}
__device__ __forceinline__ int edge_at(const void* ei, long long pos) {
    int v;
    if (g_idx64) v = (int)((const long long*)ei)[pos];
    else         v = ((const int*)ei)[pos];
    return clampi(v, 0, N_NODES - 1);
}

// ---------------- weight + input split ----------------
__global__ void k_wsplit(const float* Wl1, const float* Wr1, const float* Wl2, const float* Wr2,
                         const float* Wl3, const float* Wr3, const float* Wl4, const float* Wr4) {
    int i = blockIdx.x * 256 + threadIdx.x;
    const float* src[8] = {Wl1, Wr1, Wl2, Wr2, Wl3, Wr3, Wl4, Wr4};
    const int cnt[8] = {16384, 16384, 16384, 16384, 8192, 8192, 4096, 4096};
    // per layer: [Wl_h, Wl_l, Wr_h, Wr_l]; hi at dh, lo at dh+cnt
    const int dh[8] = {0, 32768, 65536, 98304, 131072, 147456, 163840, 172032};
    #pragma unroll
    for (int s = 0; s < 8; s++) {
        if (i < cnt[s]) {
            float v = src[s][i];
            __half h = __float2half_rn(v);
            g_w16[dh[s] + i] = h;
            g_w16[dh[s] + cnt[s] + i] = __float2half_rn(v - __half2float(h));
        }
    }
}

__global__ void k_xsplit(const float* __restrict__ x) {
    int i = blockIdx.x * blockDim.x + threadIdx.x;
    if (i < N_NODES * 128) {
        float v = x[i];
        __half h = __float2half_rn(v);
        g_xh[i] = h;
        g_xl[i] = __float2half_rn(v - __half2float(h));
    }
}

// ---------------- CSR build ----------------
__global__ void k_zero_deg() {
    int i = blockIdx.x * blockDim.x + threadIdx.x;
    if (i < N_NODES) g_deg[i] = 0;
}
__global__ void k_count(const void* __restrict__ ei) {
    int e = blockIdx.x * blockDim.x + threadIdx.x;
    if (e < N_EDGES) atomicAdd(&g_deg[edge_at(ei, (long long)N_EDGES + e)], 1);
}
__global__ void k_bsum() {
    __shared__ int sh[256];
    int i = blockIdx.x * 256 + threadIdx.x;
    sh[threadIdx.x] = (i < N_NODES) ? g_deg[i] : 0;
    __syncthreads();
    for (int off = 128; off > 0; off >>= 1) {
        if (threadIdx.x < off) sh[threadIdx.x] += sh[threadIdx.x + off];
        __syncthreads();
    }
    if (threadIdx.x == 0) g_bsum[blockIdx.x] = sh[0];
}
__global__ void k_bscan() {
    __shared__ int sh[256];
    int t = threadIdx.x;
    int v = (t < NBLK) ? g_bsum[t] : 0;
    sh[t] = v;
    __syncthreads();
    for (int off = 1; off < 256; off <<= 1) {
        int u = (t >= off) ? sh[t - off] : 0;
        __syncthreads();
        sh[t] += u;
        __syncthreads();
    }
    if (t < NBLK) g_boff[t] = sh[t] - v;
    if (t == 0)   g_rowptr[N_NODES] = N_EDGES;
}
__global__ void k_scatter() {
    __shared__ int sh[256];
    int t = threadIdx.x;
    int i = blockIdx.x * 256 + t;
    int d = (i < N_NODES) ? g_deg[i] : 0;
    sh[t] = d;
    __syncthreads();
    for (int off = 1; off < 256; off <<= 1) {
        int u = (t >= off) ? sh[t - off] : 0;
        __syncthreads();
        sh[t] += u;
        __syncthreads();
    }
    if (i < N_NODES) {
        int base = g_boff[blockIdx.x] + sh[t] - d;
        g_rowptr[i] = base;
        g_cursor[i] = base;
        g_invdeg[i] = 1.0f / fmaxf((float)d, 1.0f);
    }
}
__global__ void k_fill(const void* __restrict__ ei) {
    int e = blockIdx.x * blockDim.x + threadIdx.x;
    if (e < N_EDGES) {
        int s = edge_at(ei, e);
        int d = edge_at(ei, (long long)N_EDGES + e);
        int pos = atomicAdd(&g_cursor[d], 1);
        pos = clampi(pos, 0, N_EDGES - 1);
        g_src[pos] = s;
    }
}

// ---------------- mean aggregation (fp32 in, fp16 hi/lo out) ----------------
// SSEL: 0 = xparam (fp32), 1 = g_haf, 2 = g_hbf. Output: g_aggh/g_aggl (width C).
template <int C, int SSEL>
__global__ void k_agg(const float4* __restrict__ xparam4) {
    const float4* feat = (SSEL == 0) ? xparam4 : (SSEL == 1) ? (const float4*)g_haf
                                                             : (const float4*)g_hbf;
    int w    = (blockIdx.x * blockDim.x + threadIdx.x) >> 5;
    int lane = threadIdx.x & 31;
    if (w >= N_NODES) return;
    int beg = g_rowptr[w], end = g_rowptr[w + 1];
    if (C == 128) {
        float4 a = make_float4(0.f, 0.f, 0.f, 0.f);
        int e = beg;
        for (; e + 1 < end; e += 2) {
            int s0 = g_src[e], s1 = g_src[e + 1];
            float4 v0 = feat[(size_t)s0 * 32 + lane];
            float4 v1 = feat[(size_t)s1 * 32 + lane];
            a.x += v0.x; a.y += v0.y; a.z += v0.z; a.w += v0.w;
            a.x += v1.x; a.y += v1.y; a.z += v1.z; a.w += v1.w;
        }
        if (e < end) {
            float4 v0 = feat[(size_t)g_src[e] * 32 + lane];
            a.x += v0.x; a.y += v0.y; a.z += v0.z; a.w += v0.w;
        }
        float iv = g_invdeg[w];
        a.x *= iv; a.y *= iv; a.z *= iv; a.w *= iv;
        size_t base = (size_t)w * 128 + lane * 4;
        __half2 h0, l0, h1, l1;
        split2(a.x, a.y, h0, l0);
        split2(a.z, a.w, h1, l1);
        *(__half2*)&g_aggh[base]     = h0;
        *(__half2*)&g_aggh[base + 2] = h1;
        *(__half2*)&g_aggl[base]     = l0;
        *(__half2*)&g_aggl[base + 2] = l1;
    } else { // C == 64
        const float2* f2 = (const float2*)feat;
        float2 a = make_float2(0.f, 0.f);
        int e = beg;
        for (; e + 1 < end; e += 2) {
            int s0 = g_src[e], s1 = g_src[e + 1];
            float2 v0 = f2[(size_t)s0 * 32 + lane];
            float2 v1 = f2[(size_t)s1 * 32 + lane];
            a.x += v0.x; a.y += v0.y;
            a.x += v1.x; a.y += v1.y;
        }
        if (e < end) {
            float2 v0 = f2[(size_t)g_src[e] * 32 + lane];
            a.x += v0.x; a.y += v0.y;
        }
        float iv = g_invdeg[w];
        a.x *= iv; a.y *= iv;
        size_t base = (size_t)w * 64 + lane * 2;
        __half2 h0, l0;
        split2(a.x, a.y, h0, l0);
        *(__half2*)&g_aggh[base] = h0;
        *(__half2*)&g_aggl[base] = l0;
    }
}

// ---------------- tensor-core SAGE layer ----------------
// out[n,co] = sum_seg A_seg[n,:] @ B_seg[co,:]^T + bias (+relu / +log_softmax)
// K' = 6*CIN segments: (agg_hi,Wl_hi)(x_hi,Wr_hi)(agg_lo,Wl_hi)(x_lo,Wr_hi)(agg_hi,Wl_lo)(x_hi,Wr_lo)
// BM = 128 rows/block, 256 threads. COUT=128: warp tile 32x64; COUT=64: warp tile 16x64.
// smem panels KP=64 halfs wide, row stride 36 words (bank-conflict-free frag loads).
template <int CIN, int COUT, bool RELU, bool LSM, int XSEL, int OSEL, int WBASE>
__launch_bounds__(256, 1)
__global__ void k_mma(const float* __restrict__ bl, float* __restrict__ dout) {
    constexpr int KP  = 64;
    constexpr int PPS = CIN / KP;           // panels per segment
    constexpr int CC  = COUT * CIN;
    constexpr int RT  = (COUT == 128) ? 2 : 1;

    __shared__ uint4 AsU4[128 * 9];
    __shared__ uint4 BsU4[128 * 9];
    unsigned* AsW = (unsigned*)AsU4;
    unsigned* BsW = (unsigned*)BsU4;

    const __half* xh = (XSEL == 0) ? g_xh : (XSEL == 1) ? g_hah : g_hbh;
    const __half* xl = (XSEL == 0) ? g_xl : (XSEL == 1) ? g_hal : g_hbl;

    const int tid = threadIdx.x, warp = tid >> 5, lane = tid & 31;
    const int g = lane >> 2, t = lane & 3;
    const int nb = blockIdx.x * 128;
    const int rowbase = (COUT == 128) ? (warp >> 1) * 32 : warp * 16;
    const int colbase = (COUT == 128) ? (warp & 1) * 64 : 0;

    float acc[RT][8][4];
    #pragma unroll
    for (int rt = 0; rt < RT; rt++)
        #pragma unroll
        for (int f = 0; f < 8; f++)
            #pragma unroll
            for (int j = 0; j < 4; j++) acc[rt][f][j] = 0.f;

    #pragma unroll
    for (int p = 0; p < 6 * PPS; p++) {
        const int seg = p / PPS;
        const int off = (p % PPS) * KP;
        const __half* Asrc = (seg == 0 || seg == 4) ? g_aggh :
                             (seg == 2)             ? g_aggl :
                             (seg == 1 || seg == 5) ? xh : xl;
        const int bo = (seg == 0 || seg == 2) ? WBASE :
                       (seg == 1 || seg == 3) ? WBASE + 2 * CC :
                       (seg == 4)             ? WBASE + CC : WBASE + 3 * CC;
        __syncthreads();
        // stage A: 128 rows x 8 uint4 (KP=64 halfs)
        #pragma unroll
        for (int it = 0; it < 4; it++) {
            int idx = tid + it * 256;
            int row = idx >> 3, q = idx & 7;
            int n = nb + row; if (n >= N_NODES) n = N_NODES - 1;
            AsU4[row * 9 + q] = ((const uint4*)Asrc)[(size_t)n * (CIN / 8) + off / 8 + q];
        }
        // stage B: COUT rows x 8 uint4
        #pragma unroll
        for (int it = 0; it < COUT / 32; it++) {
            int idx = tid + it * 256;
            int row = idx >> 3, q = idx & 7;
            BsU4[row * 9 + q] = ((const uint4*)g_w16)[(bo + row * CIN + off) / 8 + q];
        }
        __syncthreads();

        #pragma unroll
        for (int kc = 0; kc < 4; kc++) {
            unsigned a[RT][4];
            #pragma unroll
            for (int rt = 0; rt < RT; rt++) {
                int r0 = rowbase + rt * 16 + g;
                a[rt][0] = AsW[r0 * 36 + kc * 8 + t];
                a[rt][1] = AsW[(r0 + 8) * 36 + kc * 8 + t];
                a[rt][2] = AsW[r0 * 36 + kc * 8 + t + 4];
                a[rt][3] = AsW[(r0 + 8) * 36 + kc * 8 + t + 4];
            }
            unsigned b[8][2];
            #pragma unroll
            for (int f = 0; f < 8; f++) {
                int br = colbase + f * 8 + g;
                b[f][0] = BsW[br * 36 + kc * 8 + t];
                b[f][1] = BsW[br * 36 + kc * 8 + t + 4];
            }
            #pragma unroll
            for (int rt = 0; rt < RT; rt++)
                #pragma unroll
                for (int f = 0; f < 8; f++)
                    mma16816(acc[rt][f], a[rt], b[f]);
        }
    }

    // ---------------- epilogue ----------------
    if (!LSM) {
        float*  of = (OSEL == 1) ? g_haf : g_hbf;
        __half* oh = (OSEL == 1) ? g_hah : g_hbh;
        __half* ol = (OSEL == 1) ? g_hal : g_hbl;
        #pragma unroll
        for (int rt = 0; rt < RT; rt++) {
            int n0 = nb + rowbase + rt * 16 + g;
            int n1 = n0 + 8;
            #pragma unroll
            for (int f = 0; f < 8; f++) {
                int col = colbase + f * 8 + 2 * t;
                float2 bb = *(const float2*)&bl[col];
                float v0 = acc[rt][f][0] + bb.x, v1 = acc[rt][f][1] + bb.y;
                float v2 = acc[rt][f][2] + bb.x, v3 = acc[rt][f][3] + bb.y;
                if (RELU) {
                    v0 = fmaxf(v0, 0.f); v1 = fmaxf(v1, 0.f);
                    v2 = fmaxf(v2, 0.f); v3 = fmaxf(v3, 0.f);
                }
                if (n0 < N_NODES) {
                    size_t o = (size_t)n0 * COUT + col;
                    *(float2*)&of[o] = make_float2(v0, v1);
                    __half2 hh, ll; split2(v0, v1, hh, ll);
                    *(__half2*)&oh[o] = hh; *(__half2*)&ol[o] = ll;
                }
                if (n1 < N_NODES) {
                    size_t o = (size_t)n1 * COUT + col;
                    *(float2*)&of[o] = make_float2(v2, v3);
                    __half2 hh, ll; split2(v2, v3, hh, ll);
                    *(__half2*)&oh[o] = hh; *(__half2*)&ol[o] = ll;
                }
            }
        }
    } else {
        // COUT==64, RT==1: rows n0 = nb+warp*16+g, n1 = n0+8; full row in 4-lane group
        float v0[8], v1[8], w0[8], w1[8];
        float mxA = -1e30f, mxB = -1e30f;
        #pragma unroll
        for (int f = 0; f < 8; f++) {
            int col = f * 8 + 2 * t;
            float2 bb = *(const float2*)&bl[col];
            v0[f] = acc[0][f][0] + bb.x; v1[f] = acc[0][f][1] + bb.y;
            w0[f] = acc[0][f][2] + bb.x; w1[f] = acc[0][f][3] + bb.y;
            mxA = fmaxf(mxA, fmaxf(v0[f], v1[f]));
            mxB = fmaxf(mxB, fmaxf(w0[f], w1[f]));
        }
        #pragma unroll
        for (int m = 1; m < 4; m <<= 1) {
            mxA = fmaxf(mxA, __shfl_xor_sync(0xffffffffu, mxA, m));
            mxB = fmaxf(mxB, __shfl_xor_sync(0xffffffffu, mxB, m));
        }
        float sA = 0.f, sB = 0.f;
        #pragma unroll
        for (int f = 0; f < 8; f++) {
            sA += expf(v0[f] - mxA) + expf(v1[f] - mxA);
            sB += expf(w0[f] - mxB) + expf(w1[f] - mxB);
        }
        #pragma unroll
        for (int m = 1; m < 4; m <<= 1) {
            sA += __shfl_xor_sync(0xffffffffu, sA, m);
            sB += __shfl_xor_sync(0xffffffffu, sB, m);
        }
        float lA = mxA + logf(sA), lB = mxB + logf(sB);
        int n0 = nb + rowbase + g;
        int n1 = n0 + 8;
        if (n0 < N_NODES) {
            #pragma unroll
            for (int f = 0; f < 8; f++)
                *(float2*)&dout[(size_t)n0 * 64 + f * 8 + 2 * t] =
                    make_float2(v0[f] - lA, v1[f] - lA);
        }
        if (n1 < N_NODES) {
            #pragma unroll
            for (int f = 0; f < 8; f++)
                *(float2*)&dout[(size_t)n1 * 64 + f * 8 + 2 * t] =
                    make_float2(w0[f] - lB, w1[f] - lB);
        }
    }
}

// ---------------- launch ----------------
extern "C" void kernel_launch(void* const* d_in, const int* in_sizes, int n_in,
                              void* d_out, int out_size) {
    (void)in_sizes; (void)n_in; (void)out_size;
    const float4* x4  = (const float4*)d_in[0];
    const float*  x   = (const float*)d_in[0];
    const void*   ei  = d_in[1];
    const float* Wl1 = (const float*)d_in[2];
    const float* bl1 = (const float*)d_in[3];
    const float* Wr1 = (const float*)d_in[4];
    const float* Wl2 = (const float*)d_in[5];
    const float* bl2 = (const float*)d_in[6];
    const float* Wr2 = (const float*)d_in[7];
    const float* Wl3 = (const float*)d_in[8];
    const float* bl3 = (const float*)d_in[9];
    const float* Wr3 = (const float*)d_in[10];
    const float* Wl4 = (const float*)d_in[11];
    const float* bl4 = (const float*)d_in[12];
    const float* Wr4 = (const float*)d_in[13];
    float* out = (float*)d_out;

    // preprocessing
    k_detect<<<1, 32>>>((const unsigned int*)ei);
    k_wsplit<<<64, 256>>>(Wl1, Wr1, Wl2, Wr2, Wl3, Wr3, Wl4, Wr4);
    k_xsplit<<<(N_NODES * 128 + 255) / 256, 256>>>(x);
    // CSR build
    k_zero_deg<<<NBLK, 256>>>();
    k_count<<<(N_EDGES + 255) / 256, 256>>>(ei);
    k_bsum<<<NBLK, 256>>>();
    k_bscan<<<1, 256>>>();
    k_scatter<<<NBLK, 256>>>();
    k_fill<<<(N_EDGES + 255) / 256, 256>>>(ei);

    const int AGG_GRID = (N_NODES * 32 + 255) / 256;
    const int GM = (N_NODES + 127) / 128;   // 391 MMA blocks

    // L1: agg(x) ; out -> ha (relu)
    k_agg<128, 0><<<AGG_GRID, 256>>>(x4);
    k_mma<128, 128, true, false, 0, 1, 0><<<GM, 256>>>(bl1, nullptr);
    // L2: agg(haf) ; out -> hb (relu)
    k_agg<128, 1><<<AGG_GRID, 256>>>(nullptr);
    k_mma<128, 128, true, false, 1, 2, 65536><<<GM, 256>>>(bl2, nullptr);
    // L3: agg(hbf) ; out -> ha, 64-wide (relu)
    k_agg<128, 2><<<AGG_GRID, 256>>>(nullptr);
    k_mma<128, 64, true, false, 2, 1, 131072><<<GM, 256>>>(bl3, nullptr);
    // L4: agg(haf, 64-wide) ; out -> d_out (log_softmax)
    k_agg<64, 1><<<AGG_GRID, 256>>>(nullptr);
    k_mma<64, 64, false, true, 1, 0, 163840><<<GM, 256>>>(bl4, out);
}

// round 8
// speedup vs baseline: 1.5254x; 1.1419x over previous
#include <cuda_runtime.h>
#include <cuda_fp16.h>
#include <math.h>

#define N_NODES 50000
#define N_EDGES 800000
#define NBLK    ((N_NODES + 255) / 256)

// ---------------- scratch ----------------
__device__ int    g_idx64;
__device__ int    g_deg[N_NODES];
__device__ float  g_invdeg[N_NODES];
__device__ int    g_rowptr[N_NODES + 1];
__device__ int    g_cursor[N_NODES];
__device__ int    g_src[N_EDGES];
__device__ int    g_bsum[256];
__device__ int    g_boff[256];
// fp16 hi/lo planes (MMA inputs + fp16 gather sources)
__device__ __half g_xh [(size_t)N_NODES * 128];
__device__ __half g_xl [(size_t)N_NODES * 128];
__device__ __half g_aggh[(size_t)N_NODES * 128];
__device__ __half g_aggl[(size_t)N_NODES * 128];
__device__ __half g_hah[(size_t)N_NODES * 128];
__device__ __half g_hal[(size_t)N_NODES * 128];
__device__ __half g_hbh[(size_t)N_NODES * 128];
__device__ __half g_hbl[(size_t)N_NODES * 128];
// split weights: per layer [Wl_hi | Wl_lo | Wr_hi | Wr_lo], each COUT*CIN
__device__ __half g_w16[180224];

// ---------------- helpers ----------------
__device__ __forceinline__ void split2(float v0, float v1, __half2& h, __half2& l) {
    __half h0 = __float2half_rn(v0), h1 = __float2half_rn(v1);
    h = __halves2half2(h0, h1);
    l = __halves2half2(__float2half_rn(v0 - __half2float(h0)),
                       __float2half_rn(v1 - __half2float(h1)));
}

__device__ __forceinline__ void mma16816(float* d, const unsigned* a, const unsigned* b) {
    asm volatile(
        "mma.sync.aligned.m16n8k16.row.col.f32.f16.f16.f32 "
        "{%0,%1,%2,%3},{%4,%5,%6,%7},{%8,%9},{%0,%1,%2,%3};"
        : "+f"(d[0]), "+f"(d[1]), "+f"(d[2]), "+f"(d[3])
        : "r"(a[0]), "r"(a[1]), "r"(a[2]), "r"(a[3]), "r"(b[0]), "r"(b[1]));
}

__device__ __forceinline__ int clampi(int v, int lo, int hi) {
    return v < lo ? lo : (v > hi ? hi : v);
}
__device__ __forceinline__ int edge_at(const void* ei, long long pos) {
    int v;
    if (g_idx64) v = (int)((const long long*)ei)[pos];
    else         v = ((const int*)ei)[pos];
    return clampi(v, 0, N_NODES - 1);
}

// ---------------- zero + dtype detect (merged) ----------------
__global__ void k_zero_detect(const unsigned int* __restrict__ w) {
    int i = blockIdx.x * blockDim.x + threadIdx.x;
    if (i < N_NODES) g_deg[i] = 0;
    if (blockIdx.x == 0 && threadIdx.x < 32) {
        int lane = threadIdx.x;
        unsigned int v = w[2 * lane + 1] | w[2 * (lane + 32) + 1] |
                         w[2 * (lane + 64) + 1] | w[2 * (lane + 96) + 1];
        unsigned int any = __ballot_sync(0xffffffffu, v != 0u);
        if (lane == 0) g_idx64 = (any == 0u) ? 1 : 0;
    }
}

// ---------------- weight + input split ----------------
__global__ void k_wsplit(const float* Wl1, const float* Wr1, const float* Wl2, const float* Wr2,
                         const float* Wl3, const float* Wr3, const float* Wl4, const float* Wr4) {
    int i = blockIdx.x * 256 + threadIdx.x;
    const float* src[8] = {Wl1, Wr1, Wl2, Wr2, Wl3, Wr3, Wl4, Wr4};
    const int cnt[8] = {16384, 16384, 16384, 16384, 8192, 8192, 4096, 4096};
    const int dh[8] = {0, 32768, 65536, 98304, 131072, 147456, 163840, 172032};
    #pragma unroll
    for (int s = 0; s < 8; s++) {
        if (i < cnt[s]) {
            float v = src[s][i];
            __half h = __float2half_rn(v);
            g_w16[dh[s] + i] = h;
            g_w16[dh[s] + cnt[s] + i] = __float2half_rn(v - __half2float(h));
        }
    }
}

__global__ void k_xsplit(const float* __restrict__ x) {
    int i = blockIdx.x * blockDim.x + threadIdx.x;
    if (i < N_NODES * 128) {
        float v = x[i];
        __half h = __float2half_rn(v);
        g_xh[i] = h;
        g_xl[i] = __float2half_rn(v - __half2float(h));
    }
}

// ---------------- CSR build ----------------
__global__ void k_count(const void* __restrict__ ei) {
    int e = blockIdx.x * blockDim.x + threadIdx.x;
    if (e < N_EDGES) atomicAdd(&g_deg[edge_at(ei, (long long)N_EDGES + e)], 1);
}
__global__ void k_bsum() {
    __shared__ int sh[256];
    int i = blockIdx.x * 256 + threadIdx.x;
    sh[threadIdx.x] = (i < N_NODES) ? g_deg[i] : 0;
    __syncthreads();
    for (int off = 128; off > 0; off >>= 1) {
        if (threadIdx.x < off) sh[threadIdx.x] += sh[threadIdx.x + off];
        __syncthreads();
    }
    if (threadIdx.x == 0) g_bsum[blockIdx.x] = sh[0];
}
__global__ void k_bscan() {
    __shared__ int sh[256];
    int t = threadIdx.x;
    int v = (t < NBLK) ? g_bsum[t] : 0;
    sh[t] = v;
    __syncthreads();
    for (int off = 1; off < 256; off <<= 1) {
        int u = (t >= off) ? sh[t - off] : 0;
        __syncthreads();
        sh[t] += u;
        __syncthreads();
    }
    if (t < NBLK) g_boff[t] = sh[t] - v;
    if (t == 0)   g_rowptr[N_NODES] = N_EDGES;
}
__global__ void k_scatter() {
    __shared__ int sh[256];
    int t = threadIdx.x;
    int i = blockIdx.x * 256 + t;
    int d = (i < N_NODES) ? g_deg[i] : 0;
    sh[t] = d;
    __syncthreads();
    for (int off = 1; off < 256; off <<= 1) {
        int u = (t >= off) ? sh[t - off] : 0;
        __syncthreads();
        sh[t] += u;
        __syncthreads();
    }
    if (i < N_NODES) {
        int base = g_boff[blockIdx.x] + sh[t] - d;
        g_rowptr[i] = base;
        g_cursor[i] = base;
        g_invdeg[i] = 1.0f / fmaxf((float)d, 1.0f);
    }
}
__global__ void k_fill(const void* __restrict__ ei) {
    int e = blockIdx.x * blockDim.x + threadIdx.x;
    if (e < N_EDGES) {
        int s = edge_at(ei, e);
        int d = edge_at(ei, (long long)N_EDGES + e);
        int pos = atomicAdd(&g_cursor[d], 1);
        pos = clampi(pos, 0, N_EDGES - 1);
        g_src[pos] = s;
    }
}

// ---------------- mean aggregation: fp16 gathers, fp32 accumulate ----------------
// SSEL: 0 = g_xh, 1 = g_hah, 2 = g_hbh. Output: g_aggh/g_aggl (width C).
template <int C, int SSEL>
__global__ void k_agg() {
    const __half* feat = (SSEL == 0) ? g_xh : (SSEL == 1) ? g_hah : g_hbh;
    int w    = (blockIdx.x * blockDim.x + threadIdx.x) >> 5;
    int lane = threadIdx.x & 31;
    if (w >= N_NODES) return;
    int beg = g_rowptr[w], end = g_rowptr[w + 1];
    if (C == 128) {
        // lane owns channels [lane*4, lane*4+4): one 8B load per edge
        const uint2* f = (const uint2*)feat;   // 32 uint2 per 128-ch row
        float a0 = 0.f, a1 = 0.f, a2 = 0.f, a3 = 0.f;
        int e = beg;
        for (; e + 1 < end; e += 2) {
            int s0 = g_src[e], s1 = g_src[e + 1];
            uint2 r0 = f[(size_t)s0 * 32 + lane];
            uint2 r1 = f[(size_t)s1 * 32 + lane];
            float2 p0 = __half22float2(*(__half2*)&r0.x);
            float2 p1 = __half22float2(*(__half2*)&r0.y);
            float2 q0 = __half22float2(*(__half2*)&r1.x);
            float2 q1 = __half22float2(*(__half2*)&r1.y);
            a0 += p0.x + q0.x; a1 += p0.y + q0.y;
            a2 += p1.x + q1.x; a3 += p1.y + q1.y;
        }
        if (e < end) {
            uint2 r0 = f[(size_t)g_src[e] * 32 + lane];
            float2 p0 = __half22float2(*(__half2*)&r0.x);
            float2 p1 = __half22float2(*(__half2*)&r0.y);
            a0 += p0.x; a1 += p0.y; a2 += p1.x; a3 += p1.y;
        }
        float iv = g_invdeg[w];
        a0 *= iv; a1 *= iv; a2 *= iv; a3 *= iv;
        size_t base = (size_t)w * 128 + lane * 4;
        __half2 h0, l0, h1, l1;
        split2(a0, a1, h0, l0);
        split2(a2, a3, h1, l1);
        *(__half2*)&g_aggh[base]     = h0;
        *(__half2*)&g_aggh[base + 2] = h1;
        *(__half2*)&g_aggl[base]     = l0;
        *(__half2*)&g_aggl[base + 2] = l1;
    } else { // C == 64: lane owns 2 channels, one 4B load per edge
        const unsigned* f = (const unsigned*)feat;  // 32 words per 64-ch row
        float a0 = 0.f, a1 = 0.f;
        int e = beg;
        for (; e + 1 < end; e += 2) {
            int s0 = g_src[e], s1 = g_src[e + 1];
            float2 p = __half22float2(*(__half2*)&f[(size_t)s0 * 32 + lane]);
            float2 q = __half22float2(*(__half2*)&f[(size_t)s1 * 32 + lane]);
            a0 += p.x + q.x; a1 += p.y + q.y;
        }
        if (e < end) {
            float2 p = __half22float2(*(__half2*)&f[(size_t)g_src[e] * 32 + lane]);
            a0 += p.x; a1 += p.y;
        }
        float iv = g_invdeg[w];
        a0 *= iv; a1 *= iv;
        size_t base = (size_t)w * 64 + lane * 2;
        __half2 h0, l0;
        split2(a0, a1, h0, l0);
        *(__half2*)&g_aggh[base] = h0;
        *(__half2*)&g_aggl[base] = l0;
    }
}

// ---------------- tensor-core SAGE layer ----------------
// out[n,co] = sum_seg A_seg[n,:] @ B_seg[co,:]^T + bias (+relu / +log_softmax)
// K' = 6 segments: (agg_hi,Wl_hi)(x_hi,Wr_hi)(agg_lo,Wl_hi)(x_lo,Wr_hi)(agg_hi,Wl_lo)(x_hi,Wr_lo)
template <int CIN, int COUT, bool RELU, bool LSM, int XSEL, int OSEL, int WBASE>
__launch_bounds__(256, 1)
__global__ void k_mma(const float* __restrict__ bl, float* __restrict__ dout) {
    constexpr int KP  = 64;
    constexpr int PPS = CIN / KP;
    constexpr int CC  = COUT * CIN;
    constexpr int RT  = (COUT == 128) ? 2 : 1;

    __shared__ uint4 AsU4[128 * 9];
    __shared__ uint4 BsU4[128 * 9];
    unsigned* AsW = (unsigned*)AsU4;
    unsigned* BsW = (unsigned*)BsU4;

    const __half* xh = (XSEL == 0) ? g_xh : (XSEL == 1) ? g_hah : g_hbh;
    const __half* xl = (XSEL == 0) ? g_xl : (XSEL == 1) ? g_hal : g_hbl;

    const int tid = threadIdx.x, warp = tid >> 5, lane = tid & 31;
    const int g = lane >> 2, t = lane & 3;
    const int nb = blockIdx.x * 128;
    const int rowbase = (COUT == 128) ? (warp >> 1) * 32 : warp * 16;
    const int colbase = (COUT == 128) ? (warp & 1) * 64 : 0;

    float acc[RT][8][4];
    #pragma unroll
    for (int rt = 0; rt < RT; rt++)
        #pragma unroll
        for (int f = 0; f < 8; f++)
            #pragma unroll
            for (int j = 0; j < 4; j++) acc[rt][f][j] = 0.f;

    #pragma unroll
    for (int p = 0; p < 6 * PPS; p++) {
        const int seg = p / PPS;
        const int off = (p % PPS) * KP;
        const __half* Asrc = (seg == 0 || seg == 4) ? g_aggh :
                             (seg == 2)             ? g_aggl :
                             (seg == 1 || seg == 5) ? xh : xl;
        const int bo = (seg == 0 || seg == 2) ? WBASE :
                       (seg == 1 || seg == 3) ? WBASE + 2 * CC :
                       (seg == 4)             ? WBASE + CC : WBASE + 3 * CC;
        __syncthreads();
        #pragma unroll
        for (int it = 0; it < 4; it++) {
            int idx = tid + it * 256;
            int row = idx >> 3, q = idx & 7;
            int n = nb + row; if (n >= N_NODES) n = N_NODES - 1;
            AsU4[row * 9 + q] = ((const uint4*)Asrc)[(size_t)n * (CIN / 8) + off / 8 + q];
        }
        #pragma unroll
        for (int it = 0; it < COUT / 32; it++) {
            int idx = tid + it * 256;
            int row = idx >> 3, q = idx & 7;
            BsU4[row * 9 + q] = ((const uint4*)g_w16)[(bo + row * CIN + off) / 8 + q];
        }
        __syncthreads();

        #pragma unroll
        for (int kc = 0; kc < 4; kc++) {
            unsigned a[RT][4];
            #pragma unroll
            for (int rt = 0; rt < RT; rt++) {
                int r0 = rowbase + rt * 16 + g;
                a[rt][0] = AsW[r0 * 36 + kc * 8 + t];
                a[rt][1] = AsW[(r0 + 8) * 36 + kc * 8 + t];
                a[rt][2] = AsW[r0 * 36 + kc * 8 + t + 4];
                a[rt][3] = AsW[(r0 + 8) * 36 + kc * 8 + t + 4];
            }
            unsigned b[8][2];
            #pragma unroll
            for (int f = 0; f < 8; f++) {
                int br = colbase + f * 8 + g;
                b[f][0] = BsW[br * 36 + kc * 8 + t];
                b[f][1] = BsW[br * 36 + kc * 8 + t + 4];
            }
            #pragma unroll
            for (int rt = 0; rt < RT; rt++)
                #pragma unroll
                for (int f = 0; f < 8; f++)
                    mma16816(acc[rt][f], a[rt], b[f]);
        }
    }

    // ---------------- epilogue ----------------
    if (!LSM) {
        __half* oh = (OSEL == 1) ? g_hah : g_hbh;
        __half* ol = (OSEL == 1) ? g_hal : g_hbl;
        #pragma unroll
        for (int rt = 0; rt < RT; rt++) {
            int n0 = nb + rowbase + rt * 16 + g;
            int n1 = n0 + 8;
            #pragma unroll
            for (int f = 0; f < 8; f++) {
                int col = colbase + f * 8 + 2 * t;
                float2 bb = *(const float2*)&bl[col];
                float v0 = acc[rt][f][0] + bb.x, v1 = acc[rt][f][1] + bb.y;
                float v2 = acc[rt][f][2] + bb.x, v3 = acc[rt][f][3] + bb.y;
                if (RELU) {
                    v0 = fmaxf(v0, 0.f); v1 = fmaxf(v1, 0.f);
                    v2 = fmaxf(v2, 0.f); v3 = fmaxf(v3, 0.f);
                }
                if (n0 < N_NODES) {
                    size_t o = (size_t)n0 * COUT + col;
                    __half2 hh, ll; split2(v0, v1, hh, ll);
                    *(__half2*)&oh[o] = hh; *(__half2*)&ol[o] = ll;
                }
                if (n1 < N_NODES) {
                    size_t o = (size_t)n1 * COUT + col;
                    __half2 hh, ll; split2(v2, v3, hh, ll);
                    *(__half2*)&oh[o] = hh; *(__half2*)&ol[o] = ll;
                }
            }
        }
    } else {
        float v0[8], v1[8], w0[8], w1[8];
        float mxA = -1e30f, mxB = -1e30f;
        #pragma unroll
        for (int f = 0; f < 8; f++) {
            int col = f * 8 + 2 * t;
            float2 bb = *(const float2*)&bl[col];
            v0[f] = acc[0][f][0] + bb.x; v1[f] = acc[0][f][1] + bb.y;
            w0[f] = acc[0][f][2] + bb.x; w1[f] = acc[0][f][3] + bb.y;
            mxA = fmaxf(mxA, fmaxf(v0[f], v1[f]));
            mxB = fmaxf(mxB, fmaxf(w0[f], w1[f]));
        }
        #pragma unroll
        for (int m = 1; m < 4; m <<= 1) {
            mxA = fmaxf(mxA, __shfl_xor_sync(0xffffffffu, mxA, m));
            mxB = fmaxf(mxB, __shfl_xor_sync(0xffffffffu, mxB, m));
        }
        float sA = 0.f, sB = 0.f;
        #pragma unroll
        for (int f = 0; f < 8; f++) {
            sA += expf(v0[f] - mxA) + expf(v1[f] - mxA);
            sB += expf(w0[f] - mxB) + expf(w1[f] - mxB);
        }
        #pragma unroll
        for (int m = 1; m < 4; m <<= 1) {
            sA += __shfl_xor_sync(0xffffffffu, sA, m);
            sB += __shfl_xor_sync(0xffffffffu, sB, m);
        }
        float lA = mxA + logf(sA), lB = mxB + logf(sB);
        int n0 = nb + rowbase + g;
        int n1 = n0 + 8;
        if (n0 < N_NODES) {
            #pragma unroll
            for (int f = 0; f < 8; f++)
                *(float2*)&dout[(size_t)n0 * 64 + f * 8 + 2 * t] =
                    make_float2(v0[f] - lA, v1[f] - lA);
        }
        if (n1 < N_NODES) {
            #pragma unroll
            for (int f = 0; f < 8; f++)
                *(float2*)&dout[(size_t)n1 * 64 + f * 8 + 2 * t] =
                    make_float2(w0[f] - lB, w1[f] - lB);
        }
    }
}

// ---------------- launch ----------------
extern "C" void kernel_launch(void* const* d_in, const int* in_sizes, int n_in,
                              void* d_out, int out_size) {
    (void)in_sizes; (void)n_in; (void)out_size;
    const float* x   = (const float*)d_in[0];
    const void*  ei  = d_in[1];
    const float* Wl1 = (const float*)d_in[2];
    const float* bl1 = (const float*)d_in[3];
    const float* Wr1 = (const float*)d_in[4];
    const float* Wl2 = (const float*)d_in[5];
    const float* bl2 = (const float*)d_in[6];
    const float* Wr2 = (const float*)d_in[7];
    const float* Wl3 = (const float*)d_in[8];
    const float* bl3 = (const float*)d_in[9];
    const float* Wr3 = (const float*)d_in[10];
    const float* Wl4 = (const float*)d_in[11];
    const float* bl4 = (const float*)d_in[12];
    const float* Wr4 = (const float*)d_in[13];
    float* out = (float*)d_out;

    // preprocessing + CSR build
    k_zero_detect<<<NBLK, 256>>>((const unsigned int*)ei);
    k_wsplit<<<64, 256>>>(Wl1, Wr1, Wl2, Wr2, Wl3, Wr3, Wl4, Wr4);
    k_xsplit<<<(N_NODES * 128 + 255) / 256, 256>>>(x);
    k_count<<<(N_EDGES + 255) / 256, 256>>>(ei);
    k_bsum<<<NBLK, 256>>>();
    k_bscan<<<1, 256>>>();
    k_scatter<<<NBLK, 256>>>();
    k_fill<<<(N_EDGES + 255) / 256, 256>>>(ei);

    const int AGG_GRID = (N_NODES * 32 + 255) / 256;
    const int GM = (N_NODES + 127) / 128;

    // L1: agg(xh) ; MMA -> ha (relu)
    k_agg<128, 0><<<AGG_GRID, 256>>>();
    k_mma<128, 128, true, false, 0, 1, 0><<<GM, 256>>>(bl1, nullptr);
    // L2: agg(hah) ; MMA -> hb (relu)
    k_agg<128, 1><<<AGG_GRID, 256>>>();
    k_mma<128, 128, true, false, 1, 2, 65536><<<GM, 256>>>(bl2, nullptr);
    // L3: agg(hbh) ; MMA -> ha, 64-wide (relu)
    k_agg<128, 2><<<AGG_GRID, 256>>>();
    k_mma<128, 64, true, false, 2, 1, 131072><<<GM, 256>>>(bl3, nullptr);
    // L4: agg(hah, 64-wide) ; MMA -> d_out (log_softmax)
    k_agg<64, 1><<<AGG_GRID, 256>>>();
    k_mma<64, 64, false, true, 1, 0, 163840><<<GM, 256>>>(bl4, out);
}

// round 9
// speedup vs baseline: 1.7690x; 1.1597x over previous
#include <cuda_runtime.h>
#include <cuda_fp16.h>
#include <math.h>

#define N_NODES 50000
#define N_EDGES 800000
#define NBLK    ((N_NODES + 255) / 256)

// ---------------- scratch ----------------
__device__ int      g_idx64;
__device__ unsigned g_bcount = 0;
__device__ int      g_deg[N_NODES];
__device__ float    g_invdeg[N_NODES];
__device__ int      g_rowptr[N_NODES + 1];
__device__ int      g_cursor[N_NODES];
__device__ int      g_src[N_EDGES];
__device__ int      g_bsum[256];
__device__ int      g_boff[256];
// fp16 hi/lo planes (MMA inputs + fp16 gather sources)
__device__ __half g_xh [(size_t)N_NODES * 128];
__device__ __half g_xl [(size_t)N_NODES * 128];
__device__ __half g_aggh[(size_t)N_NODES * 128];
__device__ __half g_aggl[(size_t)N_NODES * 128];
__device__ __half g_hah[(size_t)N_NODES * 128];
__device__ __half g_hal[(size_t)N_NODES * 128];
__device__ __half g_hbh[(size_t)N_NODES * 128];
__device__ __half g_hbl[(size_t)N_NODES * 128];
// split weights: per layer [Wl_hi | Wl_lo | Wr_hi | Wr_lo], each COUT*CIN
__device__ __half g_w16[180224];

// ---------------- helpers ----------------
__device__ __forceinline__ void split2(float v0, float v1, __half2& h, __half2& l) {
    __half h0 = __float2half_rn(v0), h1 = __float2half_rn(v1);
    h = __halves2half2(h0, h1);
    l = __halves2half2(__float2half_rn(v0 - __half2float(h0)),
                       __float2half_rn(v1 - __half2float(h1)));
}

__device__ __forceinline__ void mma16816(float* d, const unsigned* a, const unsigned* b) {
    asm volatile(
        "mma.sync.aligned.m16n8k16.row.col.f32.f16.f16.f32 "
        "{%0,%1,%2,%3},{%4,%5,%6,%7},{%8,%9},{%0,%1,%2,%3};"
        : "+f"(d[0]), "+f"(d[1]), "+f"(d[2]), "+f"(d[3])
        : "r"(a[0]), "r"(a[1]), "r"(a[2]), "r"(a[3]), "r"(b[0]), "r"(b[1]));
}

__device__ __forceinline__ int clampi(int v, int lo, int hi) {
    return v < lo ? lo : (v > hi ? hi : v);
}
__device__ __forceinline__ int edge_at(const void* ei, long long pos) {
    int v;
    if (g_idx64) v = (int)((const long long*)ei)[pos];
    else         v = ((const int*)ei)[pos];
    return clampi(v, 0, N_NODES - 1);
}

// ---------------- merged preprocessing: zero + detect + wsplit + xsplit ----------------
__global__ void k_pre(const unsigned int* __restrict__ w, const float* __restrict__ x,
                      const float* Wl1, const float* Wr1, const float* Wl2, const float* Wr2,
                      const float* Wl3, const float* Wr3, const float* Wl4, const float* Wr4) {
    int i = blockIdx.x * 256 + threadIdx.x;
    if (i < N_NODES) g_deg[i] = 0;
    if (blockIdx.x == 0 && threadIdx.x < 32) {
        int lane = threadIdx.x;
        unsigned int v = w[2 * lane + 1] | w[2 * (lane + 32) + 1] |
                         w[2 * (lane + 64) + 1] | w[2 * (lane + 96) + 1];
        unsigned int any = __ballot_sync(0xffffffffu, v != 0u);
        if (lane == 0) g_idx64 = (any == 0u) ? 1 : 0;
    }
    if (i < N_NODES * 128) {
        float v = x[i];
        __half h = __float2half_rn(v);
        g_xh[i] = h;
        g_xl[i] = __float2half_rn(v - __half2float(h));
    }
    // weight split (first 64 blocks cover the largest count)
    {
        const float* src[8] = {Wl1, Wr1, Wl2, Wr2, Wl3, Wr3, Wl4, Wr4};
        const int cnt[8] = {16384, 16384, 16384, 16384, 8192, 8192, 4096, 4096};
        const int dh[8] = {0, 32768, 65536, 98304, 131072, 147456, 163840, 172032};
        #pragma unroll
        for (int s = 0; s < 8; s++) {
            if (i < cnt[s]) {
                float v = src[s][i];
                __half h = __float2half_rn(v);
                g_w16[dh[s] + i] = h;
                g_w16[dh[s] + cnt[s] + i] = __float2half_rn(v - __half2float(h));
            }
        }
    }
}

// ---------------- CSR build ----------------
__global__ void k_count(const void* __restrict__ ei) {
    int i = blockIdx.x * blockDim.x + threadIdx.x;
    int e0 = i * 2, e1 = i * 2 + 1;
    int d0 = (e0 < N_EDGES) ? edge_at(ei, (long long)N_EDGES + e0) : -1;
    int d1 = (e1 < N_EDGES) ? edge_at(ei, (long long)N_EDGES + e1) : -1;
    if (d0 >= 0) atomicAdd(&g_deg[d0], 1);
    if (d1 >= 0) atomicAdd(&g_deg[d1], 1);
}

// per-block sums + last-block scan of block sums (single kernel)
__global__ void k_bsumscan() {
    __shared__ int sh[256];
    __shared__ bool last;
    int i = blockIdx.x * 256 + threadIdx.x;
    sh[threadIdx.x] = (i < N_NODES) ? g_deg[i] : 0;
    __syncthreads();
    for (int off = 128; off > 0; off >>= 1) {
        if (threadIdx.x < off) sh[threadIdx.x] += sh[threadIdx.x + off];
        __syncthreads();
    }
    if (threadIdx.x == 0) {
        g_bsum[blockIdx.x] = sh[0];
        __threadfence();
        unsigned v = atomicAdd(&g_bcount, 1u);
        last = (v == gridDim.x - 1);
    }
    __syncthreads();
    if (last) {
        __threadfence();
        int t = threadIdx.x;
        int v = (t < NBLK) ? g_bsum[t] : 0;
        sh[t] = v;
        __syncthreads();
        for (int off = 1; off < 256; off <<= 1) {
            int u = (t >= off) ? sh[t - off] : 0;
            __syncthreads();
            sh[t] += u;
            __syncthreads();
        }
        if (t < NBLK) g_boff[t] = sh[t] - v;
        if (t == 0) { g_rowptr[N_NODES] = N_EDGES; g_bcount = 0; }
    }
}

__global__ void k_scatter() {
    __shared__ int sh[256];
    int t = threadIdx.x;
    int i = blockIdx.x * 256 + t;
    int d = (i < N_NODES) ? g_deg[i] : 0;
    sh[t] = d;
    __syncthreads();
    for (int off = 1; off < 256; off <<= 1) {
        int u = (t >= off) ? sh[t - off] : 0;
        __syncthreads();
        sh[t] += u;
        __syncthreads();
    }
    if (i < N_NODES) {
        int base = g_boff[blockIdx.x] + sh[t] - d;
        g_rowptr[i] = base;
        g_cursor[i] = base;
        g_invdeg[i] = 1.0f / fmaxf((float)d, 1.0f);
    }
}

__global__ void k_fill(const void* __restrict__ ei) {
    int i = blockIdx.x * blockDim.x + threadIdx.x;
    #pragma unroll
    for (int j = 0; j < 2; j++) {
        int e = i * 2 + j;
        if (e < N_EDGES) {
            int s = edge_at(ei, e);
            int d = edge_at(ei, (long long)N_EDGES + e);
            int pos = atomicAdd(&g_cursor[d], 1);
            pos = clampi(pos, 0, N_EDGES - 1);
            g_src[pos] = s;
        }
    }
}

// ---------------- mean aggregation: fp16 gathers, fp32 accumulate ----------------
// SSEL: 0 = g_xh, 1 = g_hah, 2 = g_hbh. Output: g_aggh/g_aggl (width C).
template <int C, int SSEL>
__global__ void k_agg() {
    const __half* feat = (SSEL == 0) ? g_xh : (SSEL == 1) ? g_hah : g_hbh;
    int w    = (blockIdx.x * blockDim.x + threadIdx.x) >> 5;
    int lane = threadIdx.x & 31;
    if (w >= N_NODES) return;
    int beg = g_rowptr[w], end = g_rowptr[w + 1];
    if (C == 128) {
        const uint2* f = (const uint2*)feat;
        float a0 = 0.f, a1 = 0.f, a2 = 0.f, a3 = 0.f;
        int e = beg;
        for (; e + 1 < end; e += 2) {
            int s0 = g_src[e], s1 = g_src[e + 1];
            uint2 r0 = f[(size_t)s0 * 32 + lane];
            uint2 r1 = f[(size_t)s1 * 32 + lane];
            float2 p0 = __half22float2(*(__half2*)&r0.x);
            float2 p1 = __half22float2(*(__half2*)&r0.y);
            float2 q0 = __half22float2(*(__half2*)&r1.x);
            float2 q1 = __half22float2(*(__half2*)&r1.y);
            a0 += p0.x + q0.x; a1 += p0.y + q0.y;
            a2 += p1.x + q1.x; a3 += p1.y + q1.y;
        }
        if (e < end) {
            uint2 r0 = f[(size_t)g_src[e] * 32 + lane];
            float2 p0 = __half22float2(*(__half2*)&r0.x);
            float2 p1 = __half22float2(*(__half2*)&r0.y);
            a0 += p0.x; a1 += p0.y; a2 += p1.x; a3 += p1.y;
        }
        float iv = g_invdeg[w];
        a0 *= iv; a1 *= iv; a2 *= iv; a3 *= iv;
        size_t base = (size_t)w * 128 + lane * 4;
        __half2 h0, l0, h1, l1;
        split2(a0, a1, h0, l0);
        split2(a2, a3, h1, l1);
        *(__half2*)&g_aggh[base]     = h0;
        *(__half2*)&g_aggh[base + 2] = h1;
        *(__half2*)&g_aggl[base]     = l0;
        *(__half2*)&g_aggl[base + 2] = l1;
    } else { // C == 64
        const unsigned* f = (const unsigned*)feat;
        float a0 = 0.f, a1 = 0.f;
        int e = beg;
        for (; e + 1 < end; e += 2) {
            int s0 = g_src[e], s1 = g_src[e + 1];
            float2 p = __half22float2(*(__half2*)&f[(size_t)s0 * 32 + lane]);
            float2 q = __half22float2(*(__half2*)&f[(size_t)s1 * 32 + lane]);
            a0 += p.x + q.x; a1 += p.y + q.y;
        }
        if (e < end) {
            float2 p = __half22float2(*(__half2*)&f[(size_t)g_src[e] * 32 + lane]);
            a0 += p.x; a1 += p.y;
        }
        float iv = g_invdeg[w];
        a0 *= iv; a1 *= iv;
        size_t base = (size_t)w * 64 + lane * 2;
        __half2 h0, l0;
        split2(a0, a1, h0, l0);
        *(__half2*)&g_aggh[base] = h0;
        *(__half2*)&g_aggl[base] = l0;
    }
}

// ---------------- tensor-core SAGE layer (shared-panel staging) ----------------
// Segments per 64-wide K offset, staged once each into 4 smem buffers:
//   round 0: As0=agg_hi, As1=agg_lo, Bs0=Wl_hi, Bs1=Wl_lo -> (As0,Bs0)(As0,Bs1)(As1,Bs0)
//   round 1: As0=x_hi,  As1=x_lo,  Bs0=Wr_hi, Bs1=Wr_lo -> (As0,Bs0)(As0,Bs1)(As1,Bs0)
template <int CIN, int COUT, bool RELU, bool LSM, int XSEL, int OSEL, int WBASE>
__launch_bounds__(256, 1)
__global__ void k_mma(const float* __restrict__ bl, float* __restrict__ dout) {
    constexpr int PPS = CIN / 64;
    constexpr int CC  = COUT * CIN;
    constexpr int RT  = (COUT == 128) ? 2 : 1;

    extern __shared__ uint4 smemU4[];
    uint4* As0U4 = smemU4;
    uint4* As1U4 = As0U4 + 128 * 9;
    uint4* Bs0U4 = As1U4 + 128 * 9;
    uint4* Bs1U4 = Bs0U4 + 128 * 9;

    const __half* xh = (XSEL == 0) ? g_xh : (XSEL == 1) ? g_hah : g_hbh;
    const __half* xl = (XSEL == 0) ? g_xl : (XSEL == 1) ? g_hal : g_hbl;

    const int tid = threadIdx.x, warp = tid >> 5, lane = tid & 31;
    const int g = lane >> 2, t = lane & 3;
    const int nb = blockIdx.x * 128;
    const int rowbase = (COUT == 128) ? (warp >> 1) * 32 : warp * 16;
    const int colbase = (COUT == 128) ? (warp & 1) * 64 : 0;

    float acc[RT][8][4];
    #pragma unroll
    for (int rt = 0; rt < RT; rt++)
        #pragma unroll
        for (int f = 0; f < 8; f++)
            #pragma unroll
            for (int j = 0; j < 4; j++) acc[rt][f][j] = 0.f;

    auto domma = [&](const unsigned* AW, const unsigned* BW) {
        #pragma unroll
        for (int kc = 0; kc < 4; kc++) {
            unsigned a[RT][4];
            #pragma unroll
            for (int rt = 0; rt < RT; rt++) {
                int r0 = rowbase + rt * 16 + g;
                a[rt][0] = AW[r0 * 36 + kc * 8 + t];
                a[rt][1] = AW[(r0 + 8) * 36 + kc * 8 + t];
                a[rt][2] = AW[r0 * 36 + kc * 8 + t + 4];
                a[rt][3] = AW[(r0 + 8) * 36 + kc * 8 + t + 4];
            }
            unsigned b[8][2];
            #pragma unroll
            for (int f = 0; f < 8; f++) {
                int br = colbase + f * 8 + g;
                b[f][0] = BW[br * 36 + kc * 8 + t];
                b[f][1] = BW[br * 36 + kc * 8 + t + 4];
            }
            #pragma unroll
            for (int rt = 0; rt < RT; rt++)
                #pragma unroll
                for (int f = 0; f < 8; f++)
                    mma16816(acc[rt][f], a[rt], b[f]);
        }
    };

    #pragma unroll
    for (int off4 = 0; off4 < PPS; off4++) {
        const int off = off4 * 64;
        #pragma unroll
        for (int rnd = 0; rnd < 2; rnd++) {
            const __half* A0 = (rnd == 0) ? g_aggh : xh;
            const __half* A1 = (rnd == 0) ? g_aggl : xl;
            const int b0 = WBASE + ((rnd == 0) ? 0 : 2 * CC);
            const int b1 = b0 + CC;
            __syncthreads();
            #pragma unroll
            for (int it = 0; it < 4; it++) {
                int idx = tid + it * 256;
                int row = idx >> 3, q = idx & 7;
                int n = nb + row; if (n >= N_NODES) n = N_NODES - 1;
                size_t goff = (size_t)n * (CIN / 8) + off / 8 + q;
                As0U4[row * 9 + q] = ((const uint4*)A0)[goff];
                As1U4[row * 9 + q] = ((const uint4*)A1)[goff];
            }
            #pragma unroll
            for (int it = 0; it < COUT / 32; it++) {
                int idx = tid + it * 256;
                int row = idx >> 3, q = idx & 7;
                int woff = row * CIN + off;
                Bs0U4[row * 9 + q] = ((const uint4*)g_w16)[(b0 + woff) / 8 + q];
                Bs1U4[row * 9 + q] = ((const uint4*)g_w16)[(b1 + woff) / 8 + q];
            }
            __syncthreads();
            domma((const unsigned*)As0U4, (const unsigned*)Bs0U4);
            domma((const unsigned*)As0U4, (const unsigned*)Bs1U4);
            domma((const unsigned*)As1U4, (const unsigned*)Bs0U4);
        }
    }

    // ---------------- epilogue ----------------
    if (!LSM) {
        __half* oh = (OSEL == 1) ? g_hah : g_hbh;
        __half* ol = (OSEL == 1) ? g_hal : g_hbl;
        #pragma unroll
        for (int rt = 0; rt < RT; rt++) {
            int n0 = nb + rowbase + rt * 16 + g;
            int n1 = n0 + 8;
            #pragma unroll
            for (int f = 0; f < 8; f++) {
                int col = colbase + f * 8 + 2 * t;
                float2 bb = *(const float2*)&bl[col];
                float v0 = acc[rt][f][0] + bb.x, v1 = acc[rt][f][1] + bb.y;
                float v2 = acc[rt][f][2] + bb.x, v3 = acc[rt][f][3] + bb.y;
                if (RELU) {
                    v0 = fmaxf(v0, 0.f); v1 = fmaxf(v1, 0.f);
                    v2 = fmaxf(v2, 0.f); v3 = fmaxf(v3, 0.f);
                }
                if (n0 < N_NODES) {
                    size_t o = (size_t)n0 * COUT + col;
                    __half2 hh, ll; split2(v0, v1, hh, ll);
                    *(__half2*)&oh[o] = hh; *(__half2*)&ol[o] = ll;
                }
                if (n1 < N_NODES) {
                    size_t o = (size_t)n1 * COUT + col;
                    __half2 hh, ll; split2(v2, v3, hh, ll);
                    *(__half2*)&oh[o] = hh; *(__half2*)&ol[o] = ll;
                }
            }
        }
    } else {
        float v0[8], v1[8], w0[8], w1[8];
        float mxA = -1e30f, mxB = -1e30f;
        #pragma unroll
        for (int f = 0; f < 8; f++) {
            int col = f * 8 + 2 * t;
            float2 bb = *(const float2*)&bl[col];
            v0[f] = acc[0][f][0] + bb.x; v1[f] = acc[0][f][1] + bb.y;
            w0[f] = acc[0][f][2] + bb.x; w1[f] = acc[0][f][3] + bb.y;
            mxA = fmaxf(mxA, fmaxf(v0[f], v1[f]));
            mxB = fmaxf(mxB, fmaxf(w0[f], w1[f]));
        }
        #pragma unroll
        for (int m = 1; m < 4; m <<= 1) {
            mxA = fmaxf(mxA, __shfl_xor_sync(0xffffffffu, mxA, m));
            mxB = fmaxf(mxB, __shfl_xor_sync(0xffffffffu, mxB, m));
        }
        float sA = 0.f, sB = 0.f;
        #pragma unroll
        for (int f = 0; f < 8; f++) {
            sA += expf(v0[f] - mxA) + expf(v1[f] - mxA);
            sB += expf(w0[f] - mxB) + expf(w1[f] - mxB);
        }
        #pragma unroll
        for (int m = 1; m < 4; m <<= 1) {
            sA += __shfl_xor_sync(0xffffffffu, sA, m);
            sB += __shfl_xor_sync(0xffffffffu, sB, m);
        }
        float lA = mxA + logf(sA), lB = mxB + logf(sB);
        int n0 = nb + rowbase + g;
        int n1 = n0 + 8;
        if (n0 < N_NODES) {
            #pragma unroll
            for (int f = 0; f < 8; f++)
                *(float2*)&dout[(size_t)n0 * 64 + f * 8 + 2 * t] =
                    make_float2(v0[f] - lA, v1[f] - lA);
        }
        if (n1 < N_NODES) {
            #pragma unroll
            for (int f = 0; f < 8; f++)
                *(float2*)&dout[(size_t)n1 * 64 + f * 8 + 2 * t] =
                    make_float2(w0[f] - lB, w1[f] - lB);
        }
    }
}

// ---------------- launch ----------------
extern "C" void kernel_launch(void* const* d_in, const int* in_sizes, int n_in,
                              void* d_out, int out_size) {
    (void)in_sizes; (void)n_in; (void)out_size;
    const float* x   = (const float*)d_in[0];
    const void*  ei  = d_in[1];
    const float* Wl1 = (const float*)d_in[2];
    const float* bl1 = (const float*)d_in[3];
    const float* Wr1 = (const float*)d_in[4];
    const float* Wl2 = (const float*)d_in[5];
    const float* bl2 = (const float*)d_in[6];
    const float* Wr2 = (const float*)d_in[7];
    const float* Wl3 = (const float*)d_in[8];
    const float* bl3 = (const float*)d_in[9];
    const float* Wr3 = (const float*)d_in[10];
    const float* Wl4 = (const float*)d_in[11];
    const float* bl4 = (const float*)d_in[12];
    const float* Wr4 = (const float*)d_in[13];
    float* out = (float*)d_out;

    const int SMEM = 4 * 128 * 9 * 16;   // 73728 B
    cudaFuncSetAttribute(k_mma<128,128,true ,false,0,1,0     >, cudaFuncAttributeMaxDynamicSharedMemorySize, SMEM);
    cudaFuncSetAttribute(k_mma<128,128,true ,false,1,2,65536 >, cudaFuncAttributeMaxDynamicSharedMemorySize, SMEM);
    cudaFuncSetAttribute(k_mma<128,64 ,true ,false,2,1,131072>, cudaFuncAttributeMaxDynamicSharedMemorySize, SMEM);
    cudaFuncSetAttribute(k_mma<64 ,64 ,false,true ,1,0,163840>, cudaFuncAttributeMaxDynamicSharedMemorySize, SMEM);

    // preprocessing + CSR build (5 launches)
    k_pre<<<(N_NODES * 128 + 255) / 256, 256>>>((const unsigned int*)ei, x,
                                                Wl1, Wr1, Wl2, Wr2, Wl3, Wr3, Wl4, Wr4);
    k_count<<<(N_EDGES / 2 + 255) / 256, 256>>>(ei);
    k_bsumscan<<<NBLK, 256>>>();
    k_scatter<<<NBLK, 256>>>();
    k_fill<<<(N_EDGES / 2 + 255) / 256, 256>>>(ei);

    const int AGG_GRID = (N_NODES * 32 + 255) / 256;
    const int GM = (N_NODES + 127) / 128;

    // L1: agg(xh) ; MMA -> ha (relu)            [agg is launch #6 -> ncu capture]
    k_agg<128, 0><<<AGG_GRID, 256>>>();
    k_mma<128, 128, true, false, 0, 1, 0><<<GM, 256, SMEM>>>(bl1, nullptr);
    // L2
    k_agg<128, 1><<<AGG_GRID, 256>>>();
    k_mma<128, 128, true, false, 1, 2, 65536><<<GM, 256, SMEM>>>(bl2, nullptr);
    // L3
    k_agg<128, 2><<<AGG_GRID, 256>>>();
    k_mma<128, 64, true, false, 2, 1, 131072><<<GM, 256, SMEM>>>(bl3, nullptr);
    // L4
    k_agg<64, 1><<<AGG_GRID, 256>>>();
    k_mma<64, 64, false, true, 1, 0, 163840><<<GM, 256, SMEM>>>(bl4, out);
}

// round 10
// speedup vs baseline: 1.8757x; 1.0603x over previous
#include <cuda_runtime.h>
#include <cuda_fp16.h>
#include <math.h>

#define N_NODES 50000
#define N_EDGES 800000
#define NBLK    ((N_NODES + 255) / 256)

// ---------------- scratch ----------------
__device__ int      g_idx64;
__device__ unsigned g_bcount = 0;
__device__ int      g_deg[N_NODES];
__device__ float    g_invdeg[N_NODES];
__device__ int      g_rowptr[N_NODES + 1];
__device__ int      g_cursor[N_NODES];
__device__ int      g_src[N_EDGES];
__device__ int      g_bsum[256];
__device__ int      g_boff[256];
// fp16 hi/lo planes (MMA inputs + fp16 gather sources); agg has hi only
__device__ __half g_xh [(size_t)N_NODES * 128];
__device__ __half g_xl [(size_t)N_NODES * 128];
__device__ __half g_aggh[(size_t)N_NODES * 128];
__device__ __half g_hah[(size_t)N_NODES * 128];
__device__ __half g_hal[(size_t)N_NODES * 128];
__device__ __half g_hbh[(size_t)N_NODES * 128];
__device__ __half g_hbl[(size_t)N_NODES * 128];
// split weights: per layer [Wl_hi | Wl_lo | Wr_hi | Wr_lo], each COUT*CIN
__device__ __half g_w16[180224];

// ---------------- helpers ----------------
__device__ __forceinline__ void split2(float v0, float v1, __half2& h, __half2& l) {
    __half h0 = __float2half_rn(v0), h1 = __float2half_rn(v1);
    h = __halves2half2(h0, h1);
    l = __halves2half2(__float2half_rn(v0 - __half2float(h0)),
                       __float2half_rn(v1 - __half2float(h1)));
}

__device__ __forceinline__ void mma16816(float* d, const unsigned* a, const unsigned* b) {
    asm volatile(
        "mma.sync.aligned.m16n8k16.row.col.f32.f16.f16.f32 "
        "{%0,%1,%2,%3},{%4,%5,%6,%7},{%8,%9},{%0,%1,%2,%3};"
        : "+f"(d[0]), "+f"(d[1]), "+f"(d[2]), "+f"(d[3])
        : "r"(a[0]), "r"(a[1]), "r"(a[2]), "r"(a[3]), "r"(b[0]), "r"(b[1]));
}

__device__ __forceinline__ int clampi(int v, int lo, int hi) {
    return v < lo ? lo : (v > hi ? hi : v);
}

// ---------------- merged preprocessing: zero + detect + wsplit + xsplit ----------------
__global__ void k_pre(const unsigned int* __restrict__ w, const float* __restrict__ x,
                      const float* Wl1, const float* Wr1, const float* Wl2, const float* Wr2,
                      const float* Wl3, const float* Wr3, const float* Wl4, const float* Wr4) {
    int i = blockIdx.x * 256 + threadIdx.x;
    if (i < N_NODES) g_deg[i] = 0;
    if (blockIdx.x == 0 && threadIdx.x < 32) {
        int lane = threadIdx.x;
        unsigned int v = w[2 * lane + 1] | w[2 * (lane + 32) + 1] |
                         w[2 * (lane + 64) + 1] | w[2 * (lane + 96) + 1];
        unsigned int any = __ballot_sync(0xffffffffu, v != 0u);
        if (lane == 0) g_idx64 = (any == 0u) ? 1 : 0;
    }
    if (i < N_NODES * 128) {
        float v = x[i];
        __half h = __float2half_rn(v);
        g_xh[i] = h;
        g_xl[i] = __float2half_rn(v - __half2float(h));
    }
    {
        const float* src[8] = {Wl1, Wr1, Wl2, Wr2, Wl3, Wr3, Wl4, Wr4};
        const int cnt[8] = {16384, 16384, 16384, 16384, 8192, 8192, 4096, 4096};
        const int dh[8] = {0, 32768, 65536, 98304, 131072, 147456, 163840, 172032};
        #pragma unroll
        for (int s = 0; s < 8; s++) {
            if (i < cnt[s]) {
                float v = src[s][i];
                __half h = __float2half_rn(v);
                g_w16[dh[s] + i] = h;
                g_w16[dh[s] + cnt[s] + i] = __float2half_rn(v - __half2float(h));
            }
        }
    }
}

// ---------------- CSR build (4 edges/thread, vectorized loads) ----------------
__global__ void k_count(const void* __restrict__ ei) {
    int i = blockIdx.x * blockDim.x + threadIdx.x;
    if (i * 4 >= N_EDGES) return;
    int d[4];
    if (g_idx64) {
        const ulonglong2* p = (const ulonglong2*)((const long long*)ei + N_EDGES);
        ulonglong2 a = p[i * 2], b = p[i * 2 + 1];
        d[0] = (int)a.x; d[1] = (int)a.y; d[2] = (int)b.x; d[3] = (int)b.y;
    } else {
        int4 v = ((const int4*)((const int*)ei + N_EDGES))[i];
        d[0] = v.x; d[1] = v.y; d[2] = v.z; d[3] = v.w;
    }
    #pragma unroll
    for (int j = 0; j < 4; j++)
        atomicAdd(&g_deg[clampi(d[j], 0, N_NODES - 1)], 1);
}

__global__ void k_bsumscan() {
    __shared__ int sh[256];
    __shared__ bool last;
    int i = blockIdx.x * 256 + threadIdx.x;
    sh[threadIdx.x] = (i < N_NODES) ? g_deg[i] : 0;
    __syncthreads();
    for (int off = 128; off > 0; off >>= 1) {
        if (threadIdx.x < off) sh[threadIdx.x] += sh[threadIdx.x + off];
        __syncthreads();
    }
    if (threadIdx.x == 0) {
        g_bsum[blockIdx.x] = sh[0];
        __threadfence();
        unsigned v = atomicAdd(&g_bcount, 1u);
        last = (v == gridDim.x - 1);
    }
    __syncthreads();
    if (last) {
        __threadfence();
        int t = threadIdx.x;
        int v = (t < NBLK) ? g_bsum[t] : 0;
        sh[t] = v;
        __syncthreads();
        for (int off = 1; off < 256; off <<= 1) {
            int u = (t >= off) ? sh[t - off] : 0;
            __syncthreads();
            sh[t] += u;
            __syncthreads();
        }
        if (t < NBLK) g_boff[t] = sh[t] - v;
        if (t == 0) { g_rowptr[N_NODES] = N_EDGES; g_bcount = 0; }
    }
}

__global__ void k_scatter() {
    __shared__ int sh[256];
    int t = threadIdx.x;
    int i = blockIdx.x * 256 + t;
    int d = (i < N_NODES) ? g_deg[i] : 0;
    sh[t] = d;
    __syncthreads();
    for (int off = 1; off < 256; off <<= 1) {
        int u = (t >= off) ? sh[t - off] : 0;
        __syncthreads();
        sh[t] += u;
        __syncthreads();
    }
    if (i < N_NODES) {
        int base = g_boff[blockIdx.x] + sh[t] - d;
        g_rowptr[i] = base;
        g_cursor[i] = base;
        g_invdeg[i] = 1.0f / fmaxf((float)d, 1.0f);
    }
}

__global__ void k_fill(const void* __restrict__ ei) {
    int i = blockIdx.x * blockDim.x + threadIdx.x;
    if (i * 4 >= N_EDGES) return;
    int s[4], d[4];
    if (g_idx64) {
        const ulonglong2* ps = (const ulonglong2*)ei;
        const ulonglong2* pd = (const ulonglong2*)((const long long*)ei + N_EDGES);
        ulonglong2 sa = ps[i * 2], sb = ps[i * 2 + 1];
        ulonglong2 da = pd[i * 2], db = pd[i * 2 + 1];
        s[0] = (int)sa.x; s[1] = (int)sa.y; s[2] = (int)sb.x; s[3] = (int)sb.y;
        d[0] = (int)da.x; d[1] = (int)da.y; d[2] = (int)db.x; d[3] = (int)db.y;
    } else {
        int4 sv = ((const int4*)ei)[i];
        int4 dv = ((const int4*)((const int*)ei + N_EDGES))[i];
        s[0] = sv.x; s[1] = sv.y; s[2] = sv.z; s[3] = sv.w;
        d[0] = dv.x; d[1] = dv.y; d[2] = dv.z; d[3] = dv.w;
    }
    #pragma unroll
    for (int j = 0; j < 4; j++) {
        int pos = atomicAdd(&g_cursor[clampi(d[j], 0, N_NODES - 1)], 1);
        pos = clampi(pos, 0, N_EDGES - 1);
        g_src[pos] = clampi(s[j], 0, N_NODES - 1);
    }
}

// ---------------- mean aggregation: fp16 gathers, fp32 accumulate, fp16 hi-only out --------
// SSEL: 0 = g_xh, 1 = g_hah, 2 = g_hbh. Output: g_aggh (width C).
template <int C, int SSEL>
__global__ void k_agg() {
    const __half* feat = (SSEL == 0) ? g_xh : (SSEL == 1) ? g_hah : g_hbh;
    int w    = (blockIdx.x * blockDim.x + threadIdx.x) >> 5;
    int lane = threadIdx.x & 31;
    if (w >= N_NODES) return;
    int beg = g_rowptr[w], end = g_rowptr[w + 1];
    if (C == 128) {
        const uint2* f = (const uint2*)feat;
        float a0 = 0.f, a1 = 0.f, a2 = 0.f, a3 = 0.f;
        int e = beg;
        for (; e + 1 < end; e += 2) {
            int s0 = g_src[e], s1 = g_src[e + 1];
            uint2 r0 = f[(size_t)s0 * 32 + lane];
            uint2 r1 = f[(size_t)s1 * 32 + lane];
            float2 p0 = __half22float2(*(__half2*)&r0.x);
            float2 p1 = __half22float2(*(__half2*)&r0.y);
            float2 q0 = __half22float2(*(__half2*)&r1.x);
            float2 q1 = __half22float2(*(__half2*)&r1.y);
            a0 += p0.x + q0.x; a1 += p0.y + q0.y;
            a2 += p1.x + q1.x; a3 += p1.y + q1.y;
        }
        if (e < end) {
            uint2 r0 = f[(size_t)g_src[e] * 32 + lane];
            float2 p0 = __half22float2(*(__half2*)&r0.x);
            float2 p1 = __half22float2(*(__half2*)&r0.y);
            a0 += p0.x; a1 += p0.y; a2 += p1.x; a3 += p1.y;
        }
        float iv = g_invdeg[w];
        size_t base = (size_t)w * 128 + lane * 4;
        *(__half2*)&g_aggh[base]     = __floats2half2_rn(a0 * iv, a1 * iv);
        *(__half2*)&g_aggh[base + 2] = __floats2half2_rn(a2 * iv, a3 * iv);
    } else { // C == 64
        const unsigned* f = (const unsigned*)feat;
        float a0 = 0.f, a1 = 0.f;
        int e = beg;
        for (; e + 1 < end; e += 2) {
            int s0 = g_src[e], s1 = g_src[e + 1];
            float2 p = __half22float2(*(__half2*)&f[(size_t)s0 * 32 + lane]);
            float2 q = __half22float2(*(__half2*)&f[(size_t)s1 * 32 + lane]);
            a0 += p.x + q.x; a1 += p.y + q.y;
        }
        if (e < end) {
            float2 p = __half22float2(*(__half2*)&f[(size_t)g_src[e] * 32 + lane]);
            a0 += p.x; a1 += p.y;
        }
        float iv = g_invdeg[w];
        *(__half2*)&g_aggh[(size_t)w * 64 + lane * 2] = __floats2half2_rn(a0 * iv, a1 * iv);
    }
}

// ---------------- tensor-core SAGE layer (5 K-segments) ----------------
// rnd 0 (agg): As0=agg_hi; Bs0=Wl_hi, Bs1=Wl_lo  -> (As0,Bs0)(As0,Bs1)
// rnd 1 (x):   As0=x_hi, As1=x_lo; Bs0=Wr_hi, Bs1=Wr_lo -> (As0,Bs0)(As0,Bs1)(As1,Bs0)
template <int CIN, int COUT, bool RELU, bool LSM, int XSEL, int OSEL, int WBASE>
__launch_bounds__(256, 1)
__global__ void k_mma(const float* __restrict__ bl, float* __restrict__ dout) {
    constexpr int PPS = CIN / 64;
    constexpr int CC  = COUT * CIN;
    constexpr int RT  = (COUT == 128) ? 2 : 1;

    extern __shared__ uint4 smemU4[];
    uint4* As0U4 = smemU4;
    uint4* As1U4 = As0U4 + 128 * 9;
    uint4* Bs0U4 = As1U4 + 128 * 9;
    uint4* Bs1U4 = Bs0U4 + 128 * 9;

    const __half* xh = (XSEL == 0) ? g_xh : (XSEL == 1) ? g_hah : g_hbh;
    const __half* xl = (XSEL == 0) ? g_xl : (XSEL == 1) ? g_hal : g_hbl;

    const int tid = threadIdx.x, warp = tid >> 5, lane = tid & 31;
    const int g = lane >> 2, t = lane & 3;
    const int nb = blockIdx.x * 128;
    const int rowbase = (COUT == 128) ? (warp >> 1) * 32 : warp * 16;
    const int colbase = (COUT == 128) ? (warp & 1) * 64 : 0;

    float acc[RT][8][4];
    #pragma unroll
    for (int rt = 0; rt < RT; rt++)
        #pragma unroll
        for (int f = 0; f < 8; f++)
            #pragma unroll
            for (int j = 0; j < 4; j++) acc[rt][f][j] = 0.f;

    auto domma = [&](const unsigned* AW, const unsigned* BW) {
        #pragma unroll
        for (int kc = 0; kc < 4; kc++) {
            unsigned a[RT][4];
            #pragma unroll
            for (int rt = 0; rt < RT; rt++) {
                int r0 = rowbase + rt * 16 + g;
                a[rt][0] = AW[r0 * 36 + kc * 8 + t];
                a[rt][1] = AW[(r0 + 8) * 36 + kc * 8 + t];
                a[rt][2] = AW[r0 * 36 + kc * 8 + t + 4];
                a[rt][3] = AW[(r0 + 8) * 36 + kc * 8 + t + 4];
            }
            unsigned b[8][2];
            #pragma unroll
            for (int f = 0; f < 8; f++) {
                int br = colbase + f * 8 + g;
                b[f][0] = BW[br * 36 + kc * 8 + t];
                b[f][1] = BW[br * 36 + kc * 8 + t + 4];
            }
            #pragma unroll
            for (int rt = 0; rt < RT; rt++)
                #pragma unroll
                for (int f = 0; f < 8; f++)
                    mma16816(acc[rt][f], a[rt], b[f]);
        }
    };

    #pragma unroll
    for (int off4 = 0; off4 < PPS; off4++) {
        const int off = off4 * 64;
        #pragma unroll
        for (int rnd = 0; rnd < 2; rnd++) {
            const __half* A0 = (rnd == 0) ? g_aggh : xh;
            const int b0 = WBASE + ((rnd == 0) ? 0 : 2 * CC);
            const int b1 = b0 + CC;
            __syncthreads();
            #pragma unroll
            for (int it = 0; it < 4; it++) {
                int idx = tid + it * 256;
                int row = idx >> 3, q = idx & 7;
                int n = nb + row; if (n >= N_NODES) n = N_NODES - 1;
                size_t goff = (size_t)n * (CIN / 8) + off / 8 + q;
                As0U4[row * 9 + q] = ((const uint4*)A0)[goff];
                if (rnd == 1)
                    As1U4[row * 9 + q] = ((const uint4*)xl)[goff];
            }
            #pragma unroll
            for (int it = 0; it < COUT / 32; it++) {
                int idx = tid + it * 256;
                int row = idx >> 3, q = idx & 7;
                int woff = row * CIN + off;
                Bs0U4[row * 9 + q] = ((const uint4*)g_w16)[(b0 + woff) / 8 + q];
                Bs1U4[row * 9 + q] = ((const uint4*)g_w16)[(b1 + woff) / 8 + q];
            }
            __syncthreads();
            domma((const unsigned*)As0U4, (const unsigned*)Bs0U4);
            domma((const unsigned*)As0U4, (const unsigned*)Bs1U4);
            if (rnd == 1)
                domma((const unsigned*)As1U4, (const unsigned*)Bs0U4);
        }
    }

    // ---------------- epilogue ----------------
    if (!LSM) {
        __half* oh = (OSEL == 1) ? g_hah : g_hbh;
        __half* ol = (OSEL == 1) ? g_hal : g_hbl;
        #pragma unroll
        for (int rt = 0; rt < RT; rt++) {
            int n0 = nb + rowbase + rt * 16 + g;
            int n1 = n0 + 8;
            #pragma unroll
            for (int f = 0; f < 8; f++) {
                int col = colbase + f * 8 + 2 * t;
                float2 bb = *(const float2*)&bl[col];
                float v0 = acc[rt][f][0] + bb.x, v1 = acc[rt][f][1] + bb.y;
                float v2 = acc[rt][f][2] + bb.x, v3 = acc[rt][f][3] + bb.y;
                if (RELU) {
                    v0 = fmaxf(v0, 0.f); v1 = fmaxf(v1, 0.f);
                    v2 = fmaxf(v2, 0.f); v3 = fmaxf(v3, 0.f);
                }
                if (n0 < N_NODES) {
                    size_t o = (size_t)n0 * COUT + col;
                    __half2 hh, ll; split2(v0, v1, hh, ll);
                    *(__half2*)&oh[o] = hh; *(__half2*)&ol[o] = ll;
                }
                if (n1 < N_NODES) {
                    size_t o = (size_t)n1 * COUT + col;
                    __half2 hh, ll; split2(v2, v3, hh, ll);
                    *(__half2*)&oh[o] = hh; *(__half2*)&ol[o] = ll;
                }
            }
        }
    } else {
        float v0[8], v1[8], w0[8], w1[8];
        float mxA = -1e30f, mxB = -1e30f;
        #pragma unroll
        for (int f = 0; f < 8; f++) {
            int col = f * 8 + 2 * t;
            float2 bb = *(const float2*)&bl[col];
            v0[f] = acc[0][f][0] + bb.x; v1[f] = acc[0][f][1] + bb.y;
            w0[f] = acc[0][f][2] + bb.x; w1[f] = acc[0][f][3] + bb.y;
            mxA = fmaxf(mxA, fmaxf(v0[f], v1[f]));
            mxB = fmaxf(mxB, fmaxf(w0[f], w1[f]));
        }
        #pragma unroll
        for (int m = 1; m < 4; m <<= 1) {
            mxA = fmaxf(mxA, __shfl_xor_sync(0xffffffffu, mxA, m));
            mxB = fmaxf(mxB, __shfl_xor_sync(0xffffffffu, mxB, m));
        }
        float sA = 0.f, sB = 0.f;
        #pragma unroll
        for (int f = 0; f < 8; f++) {
            sA += expf(v0[f] - mxA) + expf(v1[f] - mxA);
            sB += expf(w0[f] - mxB) + expf(w1[f] - mxB);
        }
        #pragma unroll
        for (int m = 1; m < 4; m <<= 1) {
            sA += __shfl_xor_sync(0xffffffffu, sA, m);
            sB += __shfl_xor_sync(0xffffffffu, sB, m);
        }
        float lA = mxA + logf(sA), lB = mxB + logf(sB);
        int n0 = nb + rowbase + g;
        int n1 = n0 + 8;
        if (n0 < N_NODES) {
            #pragma unroll
            for (int f = 0; f < 8; f++)
                *(float2*)&dout[(size_t)n0 * 64 + f * 8 + 2 * t] =
                    make_float2(v0[f] - lA, v1[f] - lA);
        }
        if (n1 < N_NODES) {
            #pragma unroll
            for (int f = 0; f < 8; f++)
                *(float2*)&dout[(size_t)n1 * 64 + f * 8 + 2 * t] =
                    make_float2(w0[f] - lB, w1[f] - lB);
        }
    }
}

// ---------------- launch ----------------
extern "C" void kernel_launch(void* const* d_in, const int* in_sizes, int n_in,
                              void* d_out, int out_size) {
    (void)in_sizes; (void)n_in; (void)out_size;
    const float* x   = (const float*)d_in[0];
    const void*  ei  = d_in[1];
    const float* Wl1 = (const float*)d_in[2];
    const float* bl1 = (const float*)d_in[3];
    const float* Wr1 = (const float*)d_in[4];
    const float* Wl2 = (const float*)d_in[5];
    const float* bl2 = (const float*)d_in[6];
    const float* Wr2 = (const float*)d_in[7];
    const float* Wl3 = (const float*)d_in[8];
    const float* bl3 = (const float*)d_in[9];
    const float* Wr3 = (const float*)d_in[10];
    const float* Wl4 = (const float*)d_in[11];
    const float* bl4 = (const float*)d_in[12];
    const float* Wr4 = (const float*)d_in[13];
    float* out = (float*)d_out;

    const int SMEM = 4 * 128 * 9 * 16;   // 73728 B
    cudaFuncSetAttribute(k_mma<128,128,true ,false,0,1,0     >, cudaFuncAttributeMaxDynamicSharedMemorySize, SMEM);
    cudaFuncSetAttribute(k_mma<128,128,true ,false,1,2,65536 >, cudaFuncAttributeMaxDynamicSharedMemorySize, SMEM);
    cudaFuncSetAttribute(k_mma<128,64 ,true ,false,2,1,131072>, cudaFuncAttributeMaxDynamicSharedMemorySize, SMEM);
    cudaFuncSetAttribute(k_mma<64 ,64 ,false,true ,1,0,163840>, cudaFuncAttributeMaxDynamicSharedMemorySize, SMEM);

    // preprocessing + CSR build
    k_pre<<<(N_NODES * 128 + 255) / 256, 256>>>((const unsigned int*)ei, x,
                                                Wl1, Wr1, Wl2, Wr2, Wl3, Wr3, Wl4, Wr4);
    k_count<<<(N_EDGES / 4 + 255) / 256, 256>>>(ei);
    k_bsumscan<<<NBLK, 256>>>();
    k_scatter<<<NBLK, 256>>>();
    k_fill<<<(N_EDGES / 4 + 255) / 256, 256>>>(ei);

    const int AGG_GRID = (N_NODES * 32 + 255) / 256;
    const int GM = (N_NODES + 127) / 128;

    // L1
    k_agg<128, 0><<<AGG_GRID, 256>>>();
    k_mma<128, 128, true, false, 0, 1, 0><<<GM, 256, SMEM>>>(bl1, nullptr);
    // L2
    k_agg<128, 1><<<AGG_GRID, 256>>>();
    k_mma<128, 128, true, false, 1, 2, 65536><<<GM, 256, SMEM>>>(bl2, nullptr);
    // L3
    k_agg<128, 2><<<AGG_GRID, 256>>>();
    k_mma<128, 64, true, false, 2, 1, 131072><<<GM, 256, SMEM>>>(bl3, nullptr);
    // L4
    k_agg<64, 1><<<AGG_GRID, 256>>>();
    k_mma<64, 64, false, true, 1, 0, 163840><<<GM, 256, SMEM>>>(bl4, out);
}

// round 11
// speedup vs baseline: 2.0736x; 1.1056x over previous
#include <cuda_runtime.h>
#include <cuda_fp16.h>
#include <math.h>

#define N_NODES 50000
#define N_EDGES 800000
#define NBLK    ((N_NODES + 255) / 256)

// ---------------- scratch ----------------
__device__ int      g_idx64;
__device__ unsigned g_bcount = 0;
__device__ int      g_deg[N_NODES];
__device__ float    g_invdeg[N_NODES];
__device__ int      g_rowptr[N_NODES + 1];
__device__ int      g_cursor[N_NODES];
__device__ int      g_src[N_EDGES];
__device__ int      g_bsum[256];
__device__ int      g_boff[256];
// fp16 hi/lo planes (MMA inputs + fp16 gather sources); agg has hi only
__device__ __half g_xh [(size_t)N_NODES * 128];
__device__ __half g_xl [(size_t)N_NODES * 128];
__device__ __half g_aggh[(size_t)N_NODES * 128];
__device__ __half g_hah[(size_t)N_NODES * 128];
__device__ __half g_hal[(size_t)N_NODES * 128];
__device__ __half g_hbh[(size_t)N_NODES * 128];
__device__ __half g_hbl[(size_t)N_NODES * 128];
// split weights: per layer [Wl_hi | Wl_lo | Wr_hi | Wr_lo], each COUT*CIN
// (lo planes still produced; only hi planes are consumed by the 3-segment MMA)
__device__ __half g_w16[180224];

// ---------------- helpers ----------------
__device__ __forceinline__ void split2(float v0, float v1, __half2& h, __half2& l) {
    __half h0 = __float2half_rn(v0), h1 = __float2half_rn(v1);
    h = __halves2half2(h0, h1);
    l = __halves2half2(__float2half_rn(v0 - __half2float(h0)),
                       __float2half_rn(v1 - __half2float(h1)));
}

__device__ __forceinline__ void mma16816(float* d, const unsigned* a, const unsigned* b) {
    asm volatile(
        "mma.sync.aligned.m16n8k16.row.col.f32.f16.f16.f32 "
        "{%0,%1,%2,%3},{%4,%5,%6,%7},{%8,%9},{%0,%1,%2,%3};"
        : "+f"(d[0]), "+f"(d[1]), "+f"(d[2]), "+f"(d[3])
        : "r"(a[0]), "r"(a[1]), "r"(a[2]), "r"(a[3]), "r"(b[0]), "r"(b[1]));
}

__device__ __forceinline__ int clampi(int v, int lo, int hi) {
    return v < lo ? lo : (v > hi ? hi : v);
}

// ---------------- merged preprocessing: zero + detect + wsplit + xsplit ----------------
__global__ void k_pre(const unsigned int* __restrict__ w, const float* __restrict__ x,
                      const float* Wl1, const float* Wr1, const float* Wl2, const float* Wr2,
                      const float* Wl3, const float* Wr3, const float* Wl4, const float* Wr4) {
    int i = blockIdx.x * 256 + threadIdx.x;
    if (i < N_NODES) g_deg[i] = 0;
    if (blockIdx.x == 0 && threadIdx.x < 32) {
        int lane = threadIdx.x;
        unsigned int v = w[2 * lane + 1] | w[2 * (lane + 32) + 1] |
                         w[2 * (lane + 64) + 1] | w[2 * (lane + 96) + 1];
        unsigned int any = __ballot_sync(0xffffffffu, v != 0u);
        if (lane == 0) g_idx64 = (any == 0u) ? 1 : 0;
    }
    if (i < N_NODES * 128) {
        float v = x[i];
        __half h = __float2half_rn(v);
        g_xh[i] = h;
        g_xl[i] = __float2half_rn(v - __half2float(h));
    }
    {
        const float* src[8] = {Wl1, Wr1, Wl2, Wr2, Wl3, Wr3, Wl4, Wr4};
        const int cnt[8] = {16384, 16384, 16384, 16384, 8192, 8192, 4096, 4096};
        const int dh[8] = {0, 32768, 65536, 98304, 131072, 147456, 163840, 172032};
        #pragma unroll
        for (int s = 0; s < 8; s++) {
            if (i < cnt[s]) {
                float v = src[s][i];
                __half h = __float2half_rn(v);
                g_w16[dh[s] + i] = h;
                g_w16[dh[s] + cnt[s] + i] = __float2half_rn(v - __half2float(h));
            }
        }
    }
}

// ---------------- CSR build (4 edges/thread, vectorized loads) ----------------
__global__ void k_count(const void* __restrict__ ei) {
    int i = blockIdx.x * blockDim.x + threadIdx.x;
    if (i * 4 >= N_EDGES) return;
    int d[4];
    if (g_idx64) {
        const ulonglong2* p = (const ulonglong2*)((const long long*)ei + N_EDGES);
        ulonglong2 a = p[i * 2], b = p[i * 2 + 1];
        d[0] = (int)a.x; d[1] = (int)a.y; d[2] = (int)b.x; d[3] = (int)b.y;
    } else {
        int4 v = ((const int4*)((const int*)ei + N_EDGES))[i];
        d[0] = v.x; d[1] = v.y; d[2] = v.z; d[3] = v.w;
    }
    #pragma unroll
    for (int j = 0; j < 4; j++)
        atomicAdd(&g_deg[clampi(d[j], 0, N_NODES - 1)], 1);
}

__global__ void k_bsumscan() {
    __shared__ int sh[256];
    __shared__ bool last;
    int i = blockIdx.x * 256 + threadIdx.x;
    sh[threadIdx.x] = (i < N_NODES) ? g_deg[i] : 0;
    __syncthreads();
    for (int off = 128; off > 0; off >>= 1) {
        if (threadIdx.x < off) sh[threadIdx.x] += sh[threadIdx.x + off];
        __syncthreads();
    }
    if (threadIdx.x == 0) {
        g_bsum[blockIdx.x] = sh[0];
        __threadfence();
        unsigned v = atomicAdd(&g_bcount, 1u);
        last = (v == gridDim.x - 1);
    }
    __syncthreads();
    if (last) {
        __threadfence();
        int t = threadIdx.x;
        int v = (t < NBLK) ? g_bsum[t] : 0;
        sh[t] = v;
        __syncthreads();
        for (int off = 1; off < 256; off <<= 1) {
            int u = (t >= off) ? sh[t - off] : 0;
            __syncthreads();
            sh[t] += u;
            __syncthreads();
        }
        if (t < NBLK) g_boff[t] = sh[t] - v;
        if (t == 0) { g_rowptr[N_NODES] = N_EDGES; g_bcount = 0; }
    }
}

__global__ void k_scatter() {
    __shared__ int sh[256];
    int t = threadIdx.x;
    int i = blockIdx.x * 256 + t;
    int d = (i < N_NODES) ? g_deg[i] : 0;
    sh[t] = d;
    __syncthreads();
    for (int off = 1; off < 256; off <<= 1) {
        int u = (t >= off) ? sh[t - off] : 0;
        __syncthreads();
        sh[t] += u;
        __syncthreads();
    }
    if (i < N_NODES) {
        int base = g_boff[blockIdx.x] + sh[t] - d;
        g_rowptr[i] = base;
        g_cursor[i] = base;
        g_invdeg[i] = 1.0f / fmaxf((float)d, 1.0f);
    }
}

__global__ void k_fill(const void* __restrict__ ei) {
    int i = blockIdx.x * blockDim.x + threadIdx.x;
    if (i * 4 >= N_EDGES) return;
    int s[4], d[4];
    if (g_idx64) {
        const ulonglong2* ps = (const ulonglong2*)ei;
        const ulonglong2* pd = (const ulonglong2*)((const long long*)ei + N_EDGES);
        ulonglong2 sa = ps[i * 2], sb = ps[i * 2 + 1];
        ulonglong2 da = pd[i * 2], db = pd[i * 2 + 1];
        s[0] = (int)sa.x; s[1] = (int)sa.y; s[2] = (int)sb.x; s[3] = (int)sb.y;
        d[0] = (int)da.x; d[1] = (int)da.y; d[2] = (int)db.x; d[3] = (int)db.y;
    } else {
        int4 sv = ((const int4*)ei)[i];
        int4 dv = ((const int4*)((const int*)ei + N_EDGES))[i];
        s[0] = sv.x; s[1] = sv.y; s[2] = sv.z; s[3] = sv.w;
        d[0] = dv.x; d[1] = dv.y; d[2] = dv.z; d[3] = dv.w;
    }
    #pragma unroll
    for (int j = 0; j < 4; j++) {
        int pos = atomicAdd(&g_cursor[clampi(d[j], 0, N_NODES - 1)], 1);
        pos = clampi(pos, 0, N_EDGES - 1);
        g_src[pos] = clampi(s[j], 0, N_NODES - 1);
    }
}

// ---------------- mean aggregation: fp16 gathers, fp32 accumulate, fp16 hi-only out --------
// SSEL: 0 = g_xh, 1 = g_hah, 2 = g_hbh. Output: g_aggh (width C).
template <int C, int SSEL>
__global__ void k_agg() {
    const __half* feat = (SSEL == 0) ? g_xh : (SSEL == 1) ? g_hah : g_hbh;
    int w    = (blockIdx.x * blockDim.x + threadIdx.x) >> 5;
    int lane = threadIdx.x & 31;
    if (w >= N_NODES) return;
    int beg = g_rowptr[w], end = g_rowptr[w + 1];
    if (C == 128) {
        const uint2* f = (const uint2*)feat;
        float a0 = 0.f, a1 = 0.f, a2 = 0.f, a3 = 0.f;
        int e = beg;
        for (; e + 1 < end; e += 2) {
            int s0 = g_src[e], s1 = g_src[e + 1];
            uint2 r0 = f[(size_t)s0 * 32 + lane];
            uint2 r1 = f[(size_t)s1 * 32 + lane];
            float2 p0 = __half22float2(*(__half2*)&r0.x);
            float2 p1 = __half22float2(*(__half2*)&r0.y);
            float2 q0 = __half22float2(*(__half2*)&r1.x);
            float2 q1 = __half22float2(*(__half2*)&r1.y);
            a0 += p0.x + q0.x; a1 += p0.y + q0.y;
            a2 += p1.x + q1.x; a3 += p1.y + q1.y;
        }
        if (e < end) {
            uint2 r0 = f[(size_t)g_src[e] * 32 + lane];
            float2 p0 = __half22float2(*(__half2*)&r0.x);
            float2 p1 = __half22float2(*(__half2*)&r0.y);
            a0 += p0.x; a1 += p0.y; a2 += p1.x; a3 += p1.y;
        }
        float iv = g_invdeg[w];
        size_t base = (size_t)w * 128 + lane * 4;
        *(__half2*)&g_aggh[base]     = __floats2half2_rn(a0 * iv, a1 * iv);
        *(__half2*)&g_aggh[base + 2] = __floats2half2_rn(a2 * iv, a3 * iv);
    } else { // C == 64
        const unsigned* f = (const unsigned*)feat;
        float a0 = 0.f, a1 = 0.f;
        int e = beg;
        for (; e + 1 < end; e += 2) {
            int s0 = g_src[e], s1 = g_src[e + 1];
            float2 p = __half22float2(*(__half2*)&f[(size_t)s0 * 32 + lane]);
            float2 q = __half22float2(*(__half2*)&f[(size_t)s1 * 32 + lane]);
            a0 += p.x + q.x; a1 += p.y + q.y;
        }
        if (e < end) {
            float2 p = __half22float2(*(__half2*)&f[(size_t)g_src[e] * 32 + lane]);
            a0 += p.x; a1 += p.y;
        }
        float iv = g_invdeg[w];
        *(__half2*)&g_aggh[(size_t)w * 64 + lane * 2] = __floats2half2_rn(a0 * iv, a1 * iv);
    }
}

// ---------------- tensor-core SAGE layer (3 K-segments) ----------------
// rnd 0 (agg): As0=agg_hi; Bs0=Wl_hi           -> (As0,Bs0)
// rnd 1 (x):   As0=x_hi, As1=x_lo; Bs0=Wr_hi   -> (As0,Bs0)(As1,Bs0)
template <int CIN, int COUT, bool RELU, bool LSM, int XSEL, int OSEL, int WBASE>
__launch_bounds__(256, 1)
__global__ void k_mma(const float* __restrict__ bl, float* __restrict__ dout) {
    constexpr int PPS = CIN / 64;
    constexpr int CC  = COUT * CIN;
    constexpr int RT  = (COUT == 128) ? 2 : 1;

    extern __shared__ uint4 smemU4[];
    uint4* As0U4 = smemU4;
    uint4* As1U4 = As0U4 + 128 * 9;
    uint4* Bs0U4 = As1U4 + 128 * 9;

    const __half* xh = (XSEL == 0) ? g_xh : (XSEL == 1) ? g_hah : g_hbh;
    const __half* xl = (XSEL == 0) ? g_xl : (XSEL == 1) ? g_hal : g_hbl;

    const int tid = threadIdx.x, warp = tid >> 5, lane = tid & 31;
    const int g = lane >> 2, t = lane & 3;
    const int nb = blockIdx.x * 128;
    const int rowbase = (COUT == 128) ? (warp >> 1) * 32 : warp * 16;
    const int colbase = (COUT == 128) ? (warp & 1) * 64 : 0;

    float acc[RT][8][4];
    #pragma unroll
    for (int rt = 0; rt < RT; rt++)
        #pragma unroll
        for (int f = 0; f < 8; f++)
            #pragma unroll
            for (int j = 0; j < 4; j++) acc[rt][f][j] = 0.f;

    auto domma = [&](const unsigned* AW, const unsigned* BW) {
        #pragma unroll
        for (int kc = 0; kc < 4; kc++) {
            unsigned a[RT][4];
            #pragma unroll
            for (int rt = 0; rt < RT; rt++) {
                int r0 = rowbase + rt * 16 + g;
                a[rt][0] = AW[r0 * 36 + kc * 8 + t];
                a[rt][1] = AW[(r0 + 8) * 36 + kc * 8 + t];
                a[rt][2] = AW[r0 * 36 + kc * 8 + t + 4];
                a[rt][3] = AW[(r0 + 8) * 36 + kc * 8 + t + 4];
            }
            unsigned b[8][2];
            #pragma unroll
            for (int f = 0; f < 8; f++) {
                int br = colbase + f * 8 + g;
                b[f][0] = BW[br * 36 + kc * 8 + t];
                b[f][1] = BW[br * 36 + kc * 8 + t + 4];
            }
            #pragma unroll
            for (int rt = 0; rt < RT; rt++)
                #pragma unroll
                for (int f = 0; f < 8; f++)
                    mma16816(acc[rt][f], a[rt], b[f]);
        }
    };

    #pragma unroll
    for (int off4 = 0; off4 < PPS; off4++) {
        const int off = off4 * 64;
        #pragma unroll
        for (int rnd = 0; rnd < 2; rnd++) {
            const __half* A0 = (rnd == 0) ? g_aggh : xh;
            const int b0 = WBASE + ((rnd == 0) ? 0 : 2 * CC);   // Wl_hi / Wr_hi
            __syncthreads();
            #pragma unroll
            for (int it = 0; it < 4; it++) {
                int idx = tid + it * 256;
                int row = idx >> 3, q = idx & 7;
                int n = nb + row; if (n >= N_NODES) n = N_NODES - 1;
                size_t goff = (size_t)n * (CIN / 8) + off / 8 + q;
                As0U4[row * 9 + q] = ((const uint4*)A0)[goff];
                if (rnd == 1)
                    As1U4[row * 9 + q] = ((const uint4*)xl)[goff];
            }
            #pragma unroll
            for (int it = 0; it < COUT / 32; it++) {
                int idx = tid + it * 256;
                int row = idx >> 3, q = idx & 7;
                Bs0U4[row * 9 + q] = ((const uint4*)g_w16)[(b0 + row * CIN + off) / 8 + q];
            }
            __syncthreads();
            domma((const unsigned*)As0U4, (const unsigned*)Bs0U4);
            if (rnd == 1)
                domma((const unsigned*)As1U4, (const unsigned*)Bs0U4);
        }
    }

    // ---------------- epilogue ----------------
    if (!LSM) {
        __half* oh = (OSEL == 1) ? g_hah : g_hbh;
        __half* ol = (OSEL == 1) ? g_hal : g_hbl;
        #pragma unroll
        for (int rt = 0; rt < RT; rt++) {
            int n0 = nb + rowbase + rt * 16 + g;
            int n1 = n0 + 8;
            #pragma unroll
            for (int f = 0; f < 8; f++) {
                int col = colbase + f * 8 + 2 * t;
                float2 bb = *(const float2*)&bl[col];
                float v0 = acc[rt][f][0] + bb.x, v1 = acc[rt][f][1] + bb.y;
                float v2 = acc[rt][f][2] + bb.x, v3 = acc[rt][f][3] + bb.y;
                if (RELU) {
                    v0 = fmaxf(v0, 0.f); v1 = fmaxf(v1, 0.f);
                    v2 = fmaxf(v2, 0.f); v3 = fmaxf(v3, 0.f);
                }
                if (n0 < N_NODES) {
                    size_t o = (size_t)n0 * COUT + col;
                    __half2 hh, ll; split2(v0, v1, hh, ll);
                    *(__half2*)&oh[o] = hh; *(__half2*)&ol[o] = ll;
                }
                if (n1 < N_NODES) {
                    size_t o = (size_t)n1 * COUT + col;
                    __half2 hh, ll; split2(v2, v3, hh, ll);
                    *(__half2*)&oh[o] = hh; *(__half2*)&ol[o] = ll;
                }
            }
        }
    } else {
        float v0[8], v1[8], w0[8], w1[8];
        float mxA = -1e30f, mxB = -1e30f;
        #pragma unroll
        for (int f = 0; f < 8; f++) {
            int col = f * 8 + 2 * t;
            float2 bb = *(const float2*)&bl[col];
            v0[f] = acc[0][f][0] + bb.x; v1[f] = acc[0][f][1] + bb.y;
            w0[f] = acc[0][f][2] + bb.x; w1[f] = acc[0][f][3] + bb.y;
            mxA = fmaxf(mxA, fmaxf(v0[f], v1[f]));
            mxB = fmaxf(mxB, fmaxf(w0[f], w1[f]));
        }
        #pragma unroll
        for (int m = 1; m < 4; m <<= 1) {
            mxA = fmaxf(mxA, __shfl_xor_sync(0xffffffffu, mxA, m));
            mxB = fmaxf(mxB, __shfl_xor_sync(0xffffffffu, mxB, m));
        }
        float sA = 0.f, sB = 0.f;
        #pragma unroll
        for (int f = 0; f < 8; f++) {
            sA += expf(v0[f] - mxA) + expf(v1[f] - mxA);
            sB += expf(w0[f] - mxB) + expf(w1[f] - mxB);
        }
        #pragma unroll
        for (int m = 1; m < 4; m <<= 1) {
            sA += __shfl_xor_sync(0xffffffffu, sA, m);
            sB += __shfl_xor_sync(0xffffffffu, sB, m);
        }
        float lA = mxA + logf(sA), lB = mxB + logf(sB);
        int n0 = nb + rowbase + g;
        int n1 = n0 + 8;
        if (n0 < N_NODES) {
            #pragma unroll
            for (int f = 0; f < 8; f++)
                *(float2*)&dout[(size_t)n0 * 64 + f * 8 + 2 * t] =
                    make_float2(v0[f] - lA, v1[f] - lA);
        }
        if (n1 < N_NODES) {
            #pragma unroll
            for (int f = 0; f < 8; f++)
                *(float2*)&dout[(size_t)n1 * 64 + f * 8 + 2 * t] =
                    make_float2(w0[f] - lB, w1[f] - lB);
        }
    }
}

// ---------------- launch ----------------
extern "C" void kernel_launch(void* const* d_in, const int* in_sizes, int n_in,
                              void* d_out, int out_size) {
    (void)in_sizes; (void)n_in; (void)out_size;
    const float* x   = (const float*)d_in[0];
    const void*  ei  = d_in[1];
    const float* Wl1 = (const float*)d_in[2];
    const float* bl1 = (const float*)d_in[3];
    const float* Wr1 = (const float*)d_in[4];
    const float* Wl2 = (const float*)d_in[5];
    const float* bl2 = (const float*)d_in[6];
    const float* Wr2 = (const float*)d_in[7];
    const float* Wl3 = (const float*)d_in[8];
    const float* bl3 = (const float*)d_in[9];
    const float* Wr3 = (const float*)d_in[10];
    const float* Wl4 = (const float*)d_in[11];
    const float* bl4 = (const float*)d_in[12];
    const float* Wr4 = (const float*)d_in[13];
    float* out = (float*)d_out;

    const int SMEM = 3 * 128 * 9 * 16;   // 55296 B
    cudaFuncSetAttribute(k_mma<128,128,true ,false,0,1,0     >, cudaFuncAttributeMaxDynamicSharedMemorySize, SMEM);
    cudaFuncSetAttribute(k_mma<128,128,true ,false,1,2,65536 >, cudaFuncAttributeMaxDynamicSharedMemorySize, SMEM);
    cudaFuncSetAttribute(k_mma<128,64 ,true ,false,2,1,131072>, cudaFuncAttributeMaxDynamicSharedMemorySize, SMEM);
    cudaFuncSetAttribute(k_mma<64 ,64 ,false,true ,1,0,163840>, cudaFuncAttributeMaxDynamicSharedMemorySize, SMEM);

    // preprocessing + CSR build
    k_pre<<<(N_NODES * 128 + 255) / 256, 256>>>((const unsigned int*)ei, x,
                                                Wl1, Wr1, Wl2, Wr2, Wl3, Wr3, Wl4, Wr4);
    k_count<<<(N_EDGES / 4 + 255) / 256, 256>>>(ei);
    k_bsumscan<<<NBLK, 256>>>();
    k_scatter<<<NBLK, 256>>>();
    k_fill<<<(N_EDGES / 4 + 255) / 256, 256>>>(ei);

    const int AGG_GRID = (N_NODES * 32 + 255) / 256;
    const int GM = (N_NODES + 127) / 128;

    // L1
    k_agg<128, 0><<<AGG_GRID, 256>>>();
    k_mma<128, 128, true, false, 0, 1, 0><<<GM, 256, SMEM>>>(bl1, nullptr);
    // L2
    k_agg<128, 1><<<AGG_GRID, 256>>>();
    k_mma<128, 128, true, false, 1, 2, 65536><<<GM, 256, SMEM>>>(bl2, nullptr);
    // L3
    k_agg<128, 2><<<AGG_GRID, 256>>>();
    k_mma<128, 64, true, false, 2, 1, 131072><<<GM, 256, SMEM>>>(bl3, nullptr);
    // L4
    k_agg<64, 1><<<AGG_GRID, 256>>>();
    k_mma<64, 64, false, true, 1, 0, 163840><<<GM, 256, SMEM>>>(bl4, out);
}

// round 12
// speedup vs baseline: 2.3377x; 1.1274x over previous
#include <cuda_runtime.h>
#include <cuda_fp16.h>
#include <math.h>

#define N_NODES 50000
#define N_EDGES 800000
#define NBLK    ((N_NODES + 255) / 256)

// ---------------- scratch ----------------
__device__ int      g_idx64;
__device__ unsigned g_bcount = 0;
__device__ int      g_deg[N_NODES];
__device__ float    g_invdeg[N_NODES];
__device__ int      g_rowptr[N_NODES + 1];
__device__ int      g_cursor[N_NODES];
__device__ int      g_src[N_EDGES];
__device__ int      g_bsum[256];
__device__ int      g_boff[256];
// fp16 activation planes (pure fp16 operands, fp32 accumulate in MMA)
__device__ __half g_xh  [(size_t)N_NODES * 128];
__device__ __half g_aggh[(size_t)N_NODES * 128];
__device__ __half g_hah [(size_t)N_NODES * 128];
__device__ __half g_hbh [(size_t)N_NODES * 128];
// fp16 weights: [Wl1|Wr1|Wl2|Wr2|Wl3|Wr3|Wl4|Wr4]
__device__ __half g_w16[90112];

// ---------------- helpers ----------------
__device__ __forceinline__ void mma16816(float* d, const unsigned* a, const unsigned* b) {
    asm volatile(
        "mma.sync.aligned.m16n8k16.row.col.f32.f16.f16.f32 "
        "{%0,%1,%2,%3},{%4,%5,%6,%7},{%8,%9},{%0,%1,%2,%3};"
        : "+f"(d[0]), "+f"(d[1]), "+f"(d[2]), "+f"(d[3])
        : "r"(a[0]), "r"(a[1]), "r"(a[2]), "r"(a[3]), "r"(b[0]), "r"(b[1]));
}

__device__ __forceinline__ int clampi(int v, int lo, int hi) {
    return v < lo ? lo : (v > hi ? hi : v);
}

// ---------------- merged preprocessing: zero + detect + wsplit + xsplit ----------------
__global__ void k_pre(const unsigned int* __restrict__ w, const float* __restrict__ x,
                      const float* Wl1, const float* Wr1, const float* Wl2, const float* Wr2,
                      const float* Wl3, const float* Wr3, const float* Wl4, const float* Wr4) {
    int i = blockIdx.x * 256 + threadIdx.x;
    if (i < N_NODES) g_deg[i] = 0;
    if (blockIdx.x == 0 && threadIdx.x < 32) {
        int lane = threadIdx.x;
        unsigned int v = w[2 * lane + 1] | w[2 * (lane + 32) + 1] |
                         w[2 * (lane + 64) + 1] | w[2 * (lane + 96) + 1];
        unsigned int any = __ballot_sync(0xffffffffu, v != 0u);
        if (lane == 0) g_idx64 = (any == 0u) ? 1 : 0;
    }
    if (i < N_NODES * 128)
        g_xh[i] = __float2half_rn(x[i]);
    {
        const float* src[8] = {Wl1, Wr1, Wl2, Wr2, Wl3, Wr3, Wl4, Wr4};
        const int cnt[8] = {16384, 16384, 16384, 16384, 8192, 8192, 4096, 4096};
        const int dh[8]  = {0, 16384, 32768, 49152, 65536, 73728, 81920, 86016};
        #pragma unroll
        for (int s = 0; s < 8; s++)
            if (i < cnt[s])
                g_w16[dh[s] + i] = __float2half_rn(src[s][i]);
    }
}

// ---------------- CSR build (4 edges/thread, vectorized loads) ----------------
__global__ void k_count(const void* __restrict__ ei) {
    int i = blockIdx.x * blockDim.x + threadIdx.x;
    if (i * 4 >= N_EDGES) return;
    int d[4];
    if (g_idx64) {
        const ulonglong2* p = (const ulonglong2*)((const long long*)ei + N_EDGES);
        ulonglong2 a = p[i * 2], b = p[i * 2 + 1];
        d[0] = (int)a.x; d[1] = (int)a.y; d[2] = (int)b.x; d[3] = (int)b.y;
    } else {
        int4 v = ((const int4*)((const int*)ei + N_EDGES))[i];
        d[0] = v.x; d[1] = v.y; d[2] = v.z; d[3] = v.w;
    }
    #pragma unroll
    for (int j = 0; j < 4; j++)
        atomicAdd(&g_deg[clampi(d[j], 0, N_NODES - 1)], 1);
}

__global__ void k_bsumscan() {
    __shared__ int sh[256];
    __shared__ bool last;
    int i = blockIdx.x * 256 + threadIdx.x;
    sh[threadIdx.x] = (i < N_NODES) ? g_deg[i] : 0;
    __syncthreads();
    for (int off = 128; off > 0; off >>= 1) {
        if (threadIdx.x < off) sh[threadIdx.x] += sh[threadIdx.x + off];
        __syncthreads();
    }
    if (threadIdx.x == 0) {
        g_bsum[blockIdx.x] = sh[0];
        __threadfence();
        unsigned v = atomicAdd(&g_bcount, 1u);
        last = (v == gridDim.x - 1);
    }
    __syncthreads();
    if (last) {
        __threadfence();
        int t = threadIdx.x;
        int v = (t < NBLK) ? g_bsum[t] : 0;
        sh[t] = v;
        __syncthreads();
        for (int off = 1; off < 256; off <<= 1) {
            int u = (t >= off) ? sh[t - off] : 0;
            __syncthreads();
            sh[t] += u;
            __syncthreads();
        }
        if (t < NBLK) g_boff[t] = sh[t] - v;
        if (t == 0) { g_rowptr[N_NODES] = N_EDGES; g_bcount = 0; }
    }
}

__global__ void k_scatter() {
    __shared__ int sh[256];
    int t = threadIdx.x;
    int i = blockIdx.x * 256 + t;
    int d = (i < N_NODES) ? g_deg[i] : 0;
    sh[t] = d;
    __syncthreads();
    for (int off = 1; off < 256; off <<= 1) {
        int u = (t >= off) ? sh[t - off] : 0;
        __syncthreads();
        sh[t] += u;
        __syncthreads();
    }
    if (i < N_NODES) {
        int base = g_boff[blockIdx.x] + sh[t] - d;
        g_rowptr[i] = base;
        g_cursor[i] = base;
        g_invdeg[i] = 1.0f / fmaxf((float)d, 1.0f);
    }
}

__global__ void k_fill(const void* __restrict__ ei) {
    int i = blockIdx.x * blockDim.x + threadIdx.x;
    if (i * 4 >= N_EDGES) return;
    int s[4], d[4];
    if (g_idx64) {
        const ulonglong2* ps = (const ulonglong2*)ei;
        const ulonglong2* pd = (const ulonglong2*)((const long long*)ei + N_EDGES);
        ulonglong2 sa = ps[i * 2], sb = ps[i * 2 + 1];
        ulonglong2 da = pd[i * 2], db = pd[i * 2 + 1];
        s[0] = (int)sa.x; s[1] = (int)sa.y; s[2] = (int)sb.x; s[3] = (int)sb.y;
        d[0] = (int)da.x; d[1] = (int)da.y; d[2] = (int)db.x; d[3] = (int)db.y;
    } else {
        int4 sv = ((const int4*)ei)[i];
        int4 dv = ((const int4*)((const int*)ei + N_EDGES))[i];
        s[0] = sv.x; s[1] = sv.y; s[2] = sv.z; s[3] = sv.w;
        d[0] = dv.x; d[1] = dv.y; d[2] = dv.z; d[3] = dv.w;
    }
    #pragma unroll
    for (int j = 0; j < 4; j++) {
        int pos = atomicAdd(&g_cursor[clampi(d[j], 0, N_NODES - 1)], 1);
        pos = clampi(pos, 0, N_EDGES - 1);
        g_src[pos] = clampi(s[j], 0, N_NODES - 1);
    }
}

// ---------------- mean aggregation: fp16 gathers, fp32 accumulate, fp16 out --------
// SSEL: 0 = g_xh, 1 = g_hah, 2 = g_hbh. Output: g_aggh (width C).
template <int C, int SSEL>
__global__ void k_agg() {
    const __half* feat = (SSEL == 0) ? g_xh : (SSEL == 1) ? g_hah : g_hbh;
    int w    = (blockIdx.x * blockDim.x + threadIdx.x) >> 5;
    int lane = threadIdx.x & 31;
    if (w >= N_NODES) return;
    int beg = g_rowptr[w], end = g_rowptr[w + 1];
    if (C == 128) {
        const uint2* f = (const uint2*)feat;
        float a0 = 0.f, a1 = 0.f, a2 = 0.f, a3 = 0.f;
        int e = beg;
        for (; e + 1 < end; e += 2) {
            int s0 = g_src[e], s1 = g_src[e + 1];
            uint2 r0 = f[(size_t)s0 * 32 + lane];
            uint2 r1 = f[(size_t)s1 * 32 + lane];
            float2 p0 = __half22float2(*(__half2*)&r0.x);
            float2 p1 = __half22float2(*(__half2*)&r0.y);
            float2 q0 = __half22float2(*(__half2*)&r1.x);
            float2 q1 = __half22float2(*(__half2*)&r1.y);
            a0 += p0.x + q0.x; a1 += p0.y + q0.y;
            a2 += p1.x + q1.x; a3 += p1.y + q1.y;
        }
        if (e < end) {
            uint2 r0 = f[(size_t)g_src[e] * 32 + lane];
            float2 p0 = __half22float2(*(__half2*)&r0.x);
            float2 p1 = __half22float2(*(__half2*)&r0.y);
            a0 += p0.x; a1 += p0.y; a2 += p1.x; a3 += p1.y;
        }
        float iv = g_invdeg[w];
        size_t base = (size_t)w * 128 + lane * 4;
        *(__half2*)&g_aggh[base]     = __floats2half2_rn(a0 * iv, a1 * iv);
        *(__half2*)&g_aggh[base + 2] = __floats2half2_rn(a2 * iv, a3 * iv);
    } else { // C == 64
        const unsigned* f = (const unsigned*)feat;
        float a0 = 0.f, a1 = 0.f;
        int e = beg;
        for (; e + 1 < end; e += 2) {
            int s0 = g_src[e], s1 = g_src[e + 1];
            float2 p = __half22float2(*(__half2*)&f[(size_t)s0 * 32 + lane]);
            float2 q = __half22float2(*(__half2*)&f[(size_t)s1 * 32 + lane]);
            a0 += p.x + q.x; a1 += p.y + q.y;
        }
        if (e < end) {
            float2 p = __half22float2(*(__half2*)&f[(size_t)g_src[e] * 32 + lane]);
            a0 += p.x; a1 += p.y;
        }
        float iv = g_invdeg[w];
        *(__half2*)&g_aggh[(size_t)w * 64 + lane * 2] = __floats2half2_rn(a0 * iv, a1 * iv);
    }
}

// ---------------- tensor-core SAGE layer (2 K-segments, pure fp16 operands) ----------------
// rnd 0: agg_hi @ Wl ; rnd 1: x_hi @ Wr.  fp32 accumulate, bias/relu/log_softmax epilogue.
template <int CIN, int COUT, bool RELU, bool LSM, int XSEL, int OSEL, int WBASE>
__launch_bounds__(256, 1)
__global__ void k_mma(const float* __restrict__ bl, float* __restrict__ dout) {
    constexpr int PPS = CIN / 64;
    constexpr int CC  = COUT * CIN;
    constexpr int RT  = (COUT == 128) ? 2 : 1;

    extern __shared__ uint4 smemU4[];
    uint4* As0U4 = smemU4;
    uint4* Bs0U4 = As0U4 + 128 * 9;

    const __half* xh = (XSEL == 0) ? g_xh : (XSEL == 1) ? g_hah : g_hbh;

    const int tid = threadIdx.x, warp = tid >> 5, lane = tid & 31;
    const int g = lane >> 2, t = lane & 3;
    const int nb = blockIdx.x * 128;
    const int rowbase = (COUT == 128) ? (warp >> 1) * 32 : warp * 16;
    const int colbase = (COUT == 128) ? (warp & 1) * 64 : 0;

    float acc[RT][8][4];
    #pragma unroll
    for (int rt = 0; rt < RT; rt++)
        #pragma unroll
        for (int f = 0; f < 8; f++)
            #pragma unroll
            for (int j = 0; j < 4; j++) acc[rt][f][j] = 0.f;

    auto domma = [&](const unsigned* AW, const unsigned* BW) {
        #pragma unroll
        for (int kc = 0; kc < 4; kc++) {
            unsigned a[RT][4];
            #pragma unroll
            for (int rt = 0; rt < RT; rt++) {
                int r0 = rowbase + rt * 16 + g;
                a[rt][0] = AW[r0 * 36 + kc * 8 + t];
                a[rt][1] = AW[(r0 + 8) * 36 + kc * 8 + t];
                a[rt][2] = AW[r0 * 36 + kc * 8 + t + 4];
                a[rt][3] = AW[(r0 + 8) * 36 + kc * 8 + t + 4];
            }
            unsigned b[8][2];
            #pragma unroll
            for (int f = 0; f < 8; f++) {
                int br = colbase + f * 8 + g;
                b[f][0] = BW[br * 36 + kc * 8 + t];
                b[f][1] = BW[br * 36 + kc * 8 + t + 4];
            }
            #pragma unroll
            for (int rt = 0; rt < RT; rt++)
                #pragma unroll
                for (int f = 0; f < 8; f++)
                    mma16816(acc[rt][f], a[rt], b[f]);
        }
    };

    #pragma unroll
    for (int off4 = 0; off4 < PPS; off4++) {
        const int off = off4 * 64;
        #pragma unroll
        for (int rnd = 0; rnd < 2; rnd++) {
            const __half* A0 = (rnd == 0) ? g_aggh : xh;
            const int b0 = WBASE + ((rnd == 0) ? 0 : CC);   // Wl / Wr
            __syncthreads();
            #pragma unroll
            for (int it = 0; it < 4; it++) {
                int idx = tid + it * 256;
                int row = idx >> 3, q = idx & 7;
                int n = nb + row; if (n >= N_NODES) n = N_NODES - 1;
                As0U4[row * 9 + q] = ((const uint4*)A0)[(size_t)n * (CIN / 8) + off / 8 + q];
            }
            #pragma unroll
            for (int it = 0; it < COUT / 32; it++) {
                int idx = tid + it * 256;
                int row = idx >> 3, q = idx & 7;
                Bs0U4[row * 9 + q] = ((const uint4*)g_w16)[(b0 + row * CIN + off) / 8 + q];
            }
            __syncthreads();
            domma((const unsigned*)As0U4, (const unsigned*)Bs0U4);
        }
    }

    // ---------------- epilogue ----------------
    if (!LSM) {
        __half* oh = (OSEL == 1) ? g_hah : g_hbh;
        #pragma unroll
        for (int rt = 0; rt < RT; rt++) {
            int n0 = nb + rowbase + rt * 16 + g;
            int n1 = n0 + 8;
            #pragma unroll
            for (int f = 0; f < 8; f++) {
                int col = colbase + f * 8 + 2 * t;
                float2 bb = *(const float2*)&bl[col];
                float v0 = acc[rt][f][0] + bb.x, v1 = acc[rt][f][1] + bb.y;
                float v2 = acc[rt][f][2] + bb.x, v3 = acc[rt][f][3] + bb.y;
                if (RELU) {
                    v0 = fmaxf(v0, 0.f); v1 = fmaxf(v1, 0.f);
                    v2 = fmaxf(v2, 0.f); v3 = fmaxf(v3, 0.f);
                }
                if (n0 < N_NODES)
                    *(__half2*)&oh[(size_t)n0 * COUT + col] = __floats2half2_rn(v0, v1);
                if (n1 < N_NODES)
                    *(__half2*)&oh[(size_t)n1 * COUT + col] = __floats2half2_rn(v2, v3);
            }
        }
    } else {
        float v0[8], v1[8], w0[8], w1[8];
        float mxA = -1e30f, mxB = -1e30f;
        #pragma unroll
        for (int f = 0; f < 8; f++) {
            int col = f * 8 + 2 * t;
            float2 bb = *(const float2*)&bl[col];
            v0[f] = acc[0][f][0] + bb.x; v1[f] = acc[0][f][1] + bb.y;
            w0[f] = acc[0][f][2] + bb.x; w1[f] = acc[0][f][3] + bb.y;
            mxA = fmaxf(mxA, fmaxf(v0[f], v1[f]));
            mxB = fmaxf(mxB, fmaxf(w0[f], w1[f]));
        }
        #pragma unroll
        for (int m = 1; m < 4; m <<= 1) {
            mxA = fmaxf(mxA, __shfl_xor_sync(0xffffffffu, mxA, m));
            mxB = fmaxf(mxB, __shfl_xor_sync(0xffffffffu, mxB, m));
        }
        float sA = 0.f, sB = 0.f;
        #pragma unroll
        for (int f = 0; f < 8; f++) {
            sA += expf(v0[f] - mxA) + expf(v1[f] - mxA);
            sB += expf(w0[f] - mxB) + expf(w1[f] - mxB);
        }
        #pragma unroll
        for (int m = 1; m < 4; m <<= 1) {
            sA += __shfl_xor_sync(0xffffffffu, sA, m);
            sB += __shfl_xor_sync(0xffffffffu, sB, m);
        }
        float lA = mxA + logf(sA), lB = mxB + logf(sB);
        int n0 = nb + rowbase + g;
        int n1 = n0 + 8;
        if (n0 < N_NODES) {
            #pragma unroll
            for (int f = 0; f < 8; f++)
                *(float2*)&dout[(size_t)n0 * 64 + f * 8 + 2 * t] =
                    make_float2(v0[f] - lA, v1[f] - lA);
        }
        if (n1 < N_NODES) {
            #pragma unroll
            for (int f = 0; f < 8; f++)
                *(float2*)&dout[(size_t)n1 * 64 + f * 8 + 2 * t] =
                    make_float2(w0[f] - lB, w1[f] - lB);
        }
    }
}

// ---------------- launch ----------------
extern "C" void kernel_launch(void* const* d_in, const int* in_sizes, int n_in,
                              void* d_out, int out_size) {
    (void)in_sizes; (void)n_in; (void)out_size;
    const float* x   = (const float*)d_in[0];
    const void*  ei  = d_in[1];
    const float* Wl1 = (const float*)d_in[2];
    const float* bl1 = (const float*)d_in[3];
    const float* Wr1 = (const float*)d_in[4];
    const float* Wl2 = (const float*)d_in[5];
    const float* bl2 = (const float*)d_in[6];
    const float* Wr2 = (const float*)d_in[7];
    const float* Wl3 = (const float*)d_in[8];
    const float* bl3 = (const float*)d_in[9];
    const float* Wr3 = (const float*)d_in[10];
    const float* Wl4 = (const float*)d_in[11];
    const float* bl4 = (const float*)d_in[12];
    const float* Wr4 = (const float*)d_in[13];
    float* out = (float*)d_out;

    const int SMEM = 2 * 128 * 9 * 16;   // 36864 B
    cudaFuncSetAttribute(k_mma<128,128,true ,false,0,1,0    >, cudaFuncAttributeMaxDynamicSharedMemorySize, SMEM);
    cudaFuncSetAttribute(k_mma<128,128,true ,false,1,2,32768>, cudaFuncAttributeMaxDynamicSharedMemorySize, SMEM);
    cudaFuncSetAttribute(k_mma<128,64 ,true ,false,2,1,65536>, cudaFuncAttributeMaxDynamicSharedMemorySize, SMEM);
    cudaFuncSetAttribute(k_mma<64 ,64 ,false,true ,1,0,81920>, cudaFuncAttributeMaxDynamicSharedMemorySize, SMEM);

    // preprocessing + CSR build
    k_pre<<<(N_NODES * 128 + 255) / 256, 256>>>((const unsigned int*)ei, x,
                                                Wl1, Wr1, Wl2, Wr2, Wl3, Wr3, Wl4, Wr4);
    k_count<<<(N_EDGES / 4 + 255) / 256, 256>>>(ei);
    k_bsumscan<<<NBLK, 256>>>();
    k_scatter<<<NBLK, 256>>>();
    k_fill<<<(N_EDGES / 4 + 255) / 256, 256>>>(ei);

    const int AGG_GRID = (N_NODES * 32 + 255) / 256;
    const int GM = (N_NODES + 127) / 128;

    // L1
    k_agg<128, 0><<<AGG_GRID, 256>>>();
    k_mma<128, 128, true, false, 0, 1, 0><<<GM, 256, SMEM>>>(bl1, nullptr);
    // L2
    k_agg<128, 1><<<AGG_GRID, 256>>>();
    k_mma<128, 128, true, false, 1, 2, 32768><<<GM, 256, SMEM>>>(bl2, nullptr);
    // L3
    k_agg<128, 2><<<AGG_GRID, 256>>>();
    k_mma<128, 64, true, false, 2, 1, 65536><<<GM, 256, SMEM>>>(bl3, nullptr);
    // L4
    k_agg<64, 1><<<AGG_GRID, 256>>>();
    k_mma<64, 64, false, true, 1, 0, 81920><<<GM, 256, SMEM>>>(bl4, out);
}